// round 2
// baseline (speedup 1.0000x reference)
#include <cuda_runtime.h>
#include <cuda_bf16.h>
#include <math.h>

// ---------------------------------------------------------------------------
// AVWDCRNN: adaptive-graph-conv GRU with HiPPO c-state.
// Shapes: B=64, T=12, N=307, Din=Dout=64, L=2, De=16, K=5 supports.
// Layouts: activations node-major [n][b][c]; supports [k][n][m]; per-node
// weights [n][(k,c)][o]. Identity support (k=0) is never multiplied — the
// per-node GEMMs read its contribution straight from the input buffer.
// ---------------------------------------------------------------------------

#define NNODE 307
#define BB    64
#define TT    12
#define DOUT  64
#define DE    16
#define KSUP  5
#define KR    4              // supports actually multiplied (skip identity)
#define CG    192            // gate gconv input channels  [x,h,c]
#define CC    128            // cand gconv input channels  [x,r*h]
#define GK    (KSUP*CG)      // 960   gate K dim
#define CK    (KSUP*CC)      // 640   cand K dim
#define NN    (NNODE*NNODE)  // 94249
#define NB    (NNODE*BB)     // 19648
#define NBO   (NB*DOUT)      // 1257472
#define TNBO  (TT*NBO)       // 15089664

// ------------------------------- scratch -----------------------------------
__device__ float g_SS [KR*NN];            // supports k=1..4: A, 2A^2-I, adjn, adjn^2
__device__ float g_Wgn[NNODE*GK*128];     // per-node gate weights   (151 MB)
__device__ float g_bgn[NNODE*128];
__device__ float g_Wcn[NNODE*CK*64];      // per-node cand weights   (50 MB)
__device__ float g_bcn[NNODE*64];
__device__ float g_XA [TNBO];             // window-averaged layer input [t][n][b][c]
__device__ float g_HS [TNBO];             // layer-0 hidden outputs [t][n][b][c]
__device__ float g_XIN[NB*CG];            // [n][b][ x | h | c ]
__device__ float g_XC [NB*CC];            // [n][b][ x | r*h ]
__device__ float g_XG [KR*NB*CG];         // S @ XIN (k=1..4)
__device__ float g_XGC[KR*NB*CC];         // S @ XC  (k=1..4)
__device__ float g_Z  [NB*DOUT];          // update gate z

// ------------------------- supports construction ----------------------------
__global__ void build_A_kernel(const float* __restrict__ E, float* __restrict__ A) {
    __shared__ float row[NNODE];
    __shared__ float er[DE];
    __shared__ float red[256];
    int i = blockIdx.x, tid = threadIdx.x;
    if (tid < DE) er[tid] = E[i*DE + tid];
    __syncthreads();
    for (int j = tid; j < NNODE; j += 256) {
        float s = 0.f;
        #pragma unroll
        for (int d = 0; d < DE; d++) s += er[d] * E[j*DE + d];
        row[j] = fmaxf(s, 0.f);
    }
    __syncthreads();
    float m = -1e30f;
    for (int j = tid; j < NNODE; j += 256) m = fmaxf(m, row[j]);
    red[tid] = m; __syncthreads();
    for (int s = 128; s > 0; s >>= 1) { if (tid < s) red[tid] = fmaxf(red[tid], red[tid+s]); __syncthreads(); }
    m = red[0]; __syncthreads();
    float sum = 0.f;
    for (int j = tid; j < NNODE; j += 256) { float e = expf(row[j]-m); row[j] = e; sum += e; }
    red[tid] = sum; __syncthreads();
    for (int s = 128; s > 0; s >>= 1) { if (tid < s) red[tid] += red[tid+s]; __syncthreads(); }
    float inv = 1.f / red[0];
    for (int j = tid; j < NNODE; j += 256) A[i*NNODE + j] = row[j] * inv;
}

__global__ void build_adjn_kernel(const float* __restrict__ adj, float* __restrict__ out) {
    __shared__ float red[256];
    int i = blockIdx.x, tid = threadIdx.x;
    float sum = 0.f;
    for (int j = tid; j < NNODE; j += 256) sum += adj[i*NNODE + j];
    red[tid] = sum; __syncthreads();
    for (int s = 128; s > 0; s >>= 1) { if (tid < s) red[tid] += red[tid+s]; __syncthreads(); }
    float inv = 1.f / (red[0] + 1e-8f);
    for (int j = tid; j < NNODE; j += 256) out[i*NNODE + j] = adj[i*NNODE + j] * inv;
}

__global__ void cheb_fix_kernel(float* __restrict__ S1) {   // S1 = 2*S1 - I (in place)
    int idx = blockIdx.x*blockDim.x + threadIdx.x;
    if (idx >= NN) return;
    float v = 2.f * S1[idx];
    if (idx / NNODE == idx % NNODE) v -= 1.f;
    S1[idx] = v;
}

// ------------------------- generic SGEMM (row-major) ------------------------
__global__ __launch_bounds__(256)
void sgemm_kernel(int M, int N, int K,
                  const float* __restrict__ A, int lda,
                  const float* __restrict__ B, int ldb,
                  float* __restrict__ C, int ldc)
{
    __shared__ float As[8][128];
    __shared__ float Bs[8][128];
    int tid = threadIdx.x;
    int m0 = blockIdx.y * 128;
    int n0 = blockIdx.x * 128;
    int tx = tid % 16, ty = tid / 16;
    float acc[8][8];
    #pragma unroll
    for (int i = 0; i < 8; i++)
        #pragma unroll
        for (int j = 0; j < 8; j++) acc[i][j] = 0.f;

    int arow = tid / 2;          // 0..127
    int acol = (tid % 2) * 4;    // 0 / 4
    int brow = tid / 32;         // 0..7
    int bcol = (tid % 32) * 4;   // 0..124

    for (int kt = 0; kt < K; kt += 8) {
        #pragma unroll
        for (int j = 0; j < 4; j++) {
            int m = m0 + arow, k = kt + acol + j;
            As[acol + j][arow] = (m < M && k < K) ? A[m*lda + k] : 0.f;
        }
        #pragma unroll
        for (int j = 0; j < 4; j++) {
            int k = kt + brow, n = n0 + bcol + j;
            Bs[brow][bcol + j] = (k < K && n < N) ? B[k*ldb + n] : 0.f;
        }
        __syncthreads();
        #pragma unroll
        for (int kk = 0; kk < 8; kk++) {
            float a[8], b[8];
            #pragma unroll
            for (int i = 0; i < 4; i++) { a[i] = As[kk][ty*4+i]; a[4+i] = As[kk][64+ty*4+i]; }
            #pragma unroll
            for (int j = 0; j < 4; j++) { b[j] = Bs[kk][tx*4+j]; b[4+j] = Bs[kk][64+tx*4+j]; }
            #pragma unroll
            for (int i = 0; i < 8; i++)
                #pragma unroll
                for (int j = 0; j < 8; j++) acc[i][j] += a[i] * b[j];
        }
        __syncthreads();
    }
    #pragma unroll
    for (int i = 0; i < 8; i++) {
        int m = m0 + (i < 4 ? ty*4+i : 64 + ty*4 + (i-4));
        if (m >= M) continue;
        #pragma unroll
        for (int j = 0; j < 8; j++) {
            int n = n0 + (j < 4 ? tx*4+j : 64 + tx*4 + (j-4));
            if (n < N) C[m*ldc + n] = acc[i][j];
        }
    }
}

// ---------------------- per-node weight projection --------------------------
__global__ void project_Wg_kernel(const float* __restrict__ E, const float* __restrict__ Wg,
                                  float* __restrict__ Wgn, int l) {
    int kc = blockIdx.x, n = blockIdx.y, o = threadIdx.x;   // grid (960, 307), block 128
    const float* er = E + n*DE;
    float acc = 0.f;
    #pragma unroll
    for (int d = 0; d < DE; d++) acc += er[d] * Wg[((l*DE + d)*GK + kc)*128 + o];
    Wgn[(n*GK + kc)*128 + o] = acc;
}
__global__ void project_Wc_kernel(const float* __restrict__ E, const float* __restrict__ Wc,
                                  float* __restrict__ Wcn, int l) {
    int kc = blockIdx.x, n = blockIdx.y, o = threadIdx.x;   // grid (640, 307), block 64
    const float* er = E + n*DE;
    float acc = 0.f;
    #pragma unroll
    for (int d = 0; d < DE; d++) acc += er[d] * Wc[((l*DE + d)*CK + kc)*64 + o];
    Wcn[(n*CK + kc)*64 + o] = acc;
}
__global__ void project_bg_kernel(const float* __restrict__ E, const float* __restrict__ bg,
                                  float* __restrict__ bgn, int l) {
    int n = blockIdx.x, o = threadIdx.x;                    // grid 307, block 128
    float acc = 0.f;
    #pragma unroll
    for (int d = 0; d < DE; d++) acc += E[n*DE+d] * bg[(l*DE + d)*128 + o];
    bgn[n*128 + o] = acc;
}
__global__ void project_bc_kernel(const float* __restrict__ E, const float* __restrict__ bc,
                                  float* __restrict__ bcn, int l) {
    int n = blockIdx.x, o = threadIdx.x;                    // grid 307, block 64
    float acc = 0.f;
    #pragma unroll
    for (int d = 0; d < DE; d++) acc += E[n*DE+d] * bc[(l*DE + d)*64 + o];
    bcn[n*64 + o] = acc;
}

// ----------------------------- data movement --------------------------------
// Layer-0: fused transpose (B,T,N,C) -> [t][n][b][c] AND 3-tap window average.
__global__ void window_avg_l0_kernel(const float* __restrict__ x, float* __restrict__ XA) {
    long long idx = (long long)blockIdx.x*blockDim.x + threadIdx.x;   // [t][n][b][c]
    if (idx >= TNBO) return;
    int c = (int)(idx % DOUT);
    int b = (int)((idx / DOUT) % BB);
    int n = (int)((idx / (DOUT*BB)) % NNODE);
    int t = (int)(idx / ((long long)DOUT*BB*NNODE));
    long long base = (((long long)b*TT + t)*NNODE + n)*DOUT + c;
    const long long dT = (long long)NNODE*DOUT;     // stride of one t in x
    float v;
    if (t == 0 || t == TT-1) v = x[base];
    else v = (x[base - dT] + x[base] + x[base + dT]) * (1.f/3.f);
    XA[idx] = v;
}

// Layer-1: window average over HS already in [t][n][b][c].
__global__ void window_avg_kernel(const float* __restrict__ IN, float* __restrict__ XA) {
    int idx = blockIdx.x*blockDim.x + threadIdx.x;   // [t][n][b][c]
    if (idx >= TNBO) return;
    int t = idx / NBO;
    if (t == 0 || t == TT-1) XA[idx] = IN[idx];
    else XA[idx] = (IN[idx-NBO] + IN[idx] + IN[idx+NBO]) * (1.f/3.f);
}

__global__ void init_state_kernel(const float* __restrict__ h0, const float* __restrict__ c0,
                                  float* __restrict__ XIN, int l) {
    int idx = blockIdx.x*blockDim.x + threadIdx.x;   // over (n,b,o)
    if (idx >= NBO) return;
    int o = idx % DOUT;
    int b = (idx / DOUT) % BB;
    int n = idx / (DOUT*BB);
    int src = ((l*BB + b)*NNODE + n)*DOUT + o;
    XIN[(n*BB + b)*CG + 64  + o] = h0[src];
    XIN[(n*BB + b)*CG + 128 + o] = c0[src];
}

__global__ void prep_step_kernel(const float* __restrict__ XA, float* __restrict__ XIN,
                                 float* __restrict__ XC, int t) {
    int idx = blockIdx.x*blockDim.x + threadIdx.x;   // over (n,b,o) = [n*64+b][o]
    if (idx >= NBO) return;
    int o  = idx % DOUT;
    int nb = idx / DOUT;
    float v = XA[t*NBO + idx];
    XIN[nb*CG + o] = v;
    XC [nb*CC + o] = v;
}

// ----------------- gate: per-node GEMM + sigmoid + r*h ----------------------
// out[b,o128] = sum_{k,c} Agate[b,(k,c)] * Wgn[n,(k,c),o],  A from XIN (k=0) / XG
__global__ __launch_bounds__(256)
void gate_gemm_kernel(const float* __restrict__ XG, const float* __restrict__ XIN,
                      const float* __restrict__ Wgn, const float* __restrict__ bgn,
                      float* __restrict__ Z, float* __restrict__ XC)
{
    const int n = blockIdx.x;
    __shared__ float As[16][64];
    __shared__ float Bs[16][128];
    int tid = threadIdx.x;
    int tx = tid % 16, ty = tid / 16;
    float acc[4][8];
    #pragma unroll
    for (int i = 0; i < 4; i++)
        #pragma unroll
        for (int j = 0; j < 8; j++) acc[i][j] = 0.f;

    const float* Wn = Wgn + (long long)n * (GK*128);
    int a_b = tid / 4;           // row b 0..63
    int a_j = (tid % 4) * 4;     // 0,4,8,12

    for (int kt = 0; kt < GK/16; kt++) {
        int kk0  = kt * 16;
        int ksup = kk0 / CG;
        int c0   = kk0 % CG;
        const float* Abase = (ksup == 0)
            ? XIN + (n*BB)*CG + c0
            : XG  + ((((long long)(ksup-1)*NNODE + n)*BB))*CG + c0;
        float4 av = *(const float4*)(Abase + a_b*CG + a_j);
        As[a_j+0][a_b] = av.x; As[a_j+1][a_b] = av.y;
        As[a_j+2][a_b] = av.z; As[a_j+3][a_b] = av.w;
        const float* Bbase = Wn + kk0*128;
        #pragma unroll
        for (int r = 0; r < 2; r++) {
            int f4 = tid + r*256;            // 0..511
            int br = f4 / 32, bc = (f4 % 32) * 4;
            *(float4*)&Bs[br][bc] = *(const float4*)(Bbase + br*128 + bc);
        }
        __syncthreads();
        #pragma unroll
        for (int kk = 0; kk < 16; kk++) {
            float a[4], b[8];
            #pragma unroll
            for (int i = 0; i < 4; i++) a[i] = As[kk][ty*4+i];
            #pragma unroll
            for (int j = 0; j < 4; j++) { b[j] = Bs[kk][tx*4+j]; b[4+j] = Bs[kk][64+tx*4+j]; }
            #pragma unroll
            for (int i = 0; i < 4; i++)
                #pragma unroll
                for (int j = 0; j < 8; j++) acc[i][j] += a[i] * b[j];
        }
        __syncthreads();
    }
    const float* brow = bgn + n*128;
    #pragma unroll
    for (int i = 0; i < 4; i++) {
        int b = ty*4 + i;
        #pragma unroll
        for (int j = 0; j < 8; j++) {
            int o = (j < 4) ? (tx*4 + j) : (64 + tx*4 + (j-4));
            float v = acc[i][j] + brow[o];
            float s = 1.f / (1.f + expf(-v));
            if (o < 64) {
                Z[(n*BB + b)*DOUT + o] = s;                       // z gate
            } else {
                int oo = o - 64;                                  // r gate -> r*h
                float h = XIN[(n*BB + b)*CG + 64 + oo];
                XC[(n*BB + b)*CC + 64 + oo] = s * h;
            }
        }
    }
}

// --------------- candidate: per-node GEMM + tanh + GRU/HiPPO ----------------
__global__ __launch_bounds__(256)
void cand_gemm_kernel(const float* __restrict__ XGC, const float* __restrict__ XC,
                      const float* __restrict__ Wcn, const float* __restrict__ bcn,
                      const float* __restrict__ Z, float* __restrict__ XIN,
                      float* __restrict__ OUT, int t, int is_final, float ca, float cb)
{
    const int n = blockIdx.x;
    __shared__ float As[16][64];
    __shared__ float Bs[16][64];
    int tid = threadIdx.x;
    int tx = tid % 16, ty = tid / 16;
    float acc[4][4];
    #pragma unroll
    for (int i = 0; i < 4; i++)
        #pragma unroll
        for (int j = 0; j < 4; j++) acc[i][j] = 0.f;

    const float* Wn = Wcn + (long long)n * (CK*64);
    int a_b = tid / 4;
    int a_j = (tid % 4) * 4;

    for (int kt = 0; kt < CK/16; kt++) {
        int kk0  = kt * 16;
        int ksup = kk0 / CC;
        int c0   = kk0 % CC;
        const float* Abase = (ksup == 0)
            ? XC  + (n*BB)*CC + c0
            : XGC + ((((long long)(ksup-1)*NNODE + n)*BB))*CC + c0;
        float4 av = *(const float4*)(Abase + a_b*CC + a_j);
        As[a_j+0][a_b] = av.x; As[a_j+1][a_b] = av.y;
        As[a_j+2][a_b] = av.z; As[a_j+3][a_b] = av.w;
        {
            int br = tid / 16, bc = (tid % 16) * 4;      // 16 rows x 64 cols, 1 float4/thread
            *(float4*)&Bs[br][bc] = *(const float4*)(Wn + (kk0 + br)*64 + bc);
        }
        __syncthreads();
        #pragma unroll
        for (int kk = 0; kk < 16; kk++) {
            float a[4], b[4];
            #pragma unroll
            for (int i = 0; i < 4; i++) a[i] = As[kk][ty*4+i];
            #pragma unroll
            for (int j = 0; j < 4; j++) b[j] = Bs[kk][tx*4+j];
            #pragma unroll
            for (int i = 0; i < 4; i++)
                #pragma unroll
                for (int j = 0; j < 4; j++) acc[i][j] += a[i] * b[j];
        }
        __syncthreads();
    }
    const float* brow = bcn + n*64;
    #pragma unroll
    for (int i = 0; i < 4; i++) {
        int b = ty*4 + i;
        #pragma unroll
        for (int j = 0; j < 4; j++) {
            int o = tx*4 + j;
            float hc = tanhf(acc[i][j] + brow[o]);
            float z  = Z[(n*BB + b)*DOUT + o];
            int ih   = (n*BB + b)*CG + 64 + o;
            float h_old = XIN[ih];
            float c_old = XIN[ih + 64];
            float h_new = z*h_old + (1.f - z)*hc;
            float c_new = ca*c_old + cb*h_new;
            XIN[ih]      = h_new;
            XIN[ih + 64] = c_new;
            if (is_final) OUT[(((long long)b*TT + t)*NNODE + n)*DOUT + o] = h_new;   // (B,T,N,O)
            else          OUT[(((long long)t*NNODE + n)*BB + b)*DOUT + o] = h_new;   // [t][n][b][o]
        }
    }
}

// -------------------------------- driver ------------------------------------
extern "C" void kernel_launch(void* const* d_in, const int* in_sizes, int n_in,
                              void* d_out, int out_size)
{
    const float* x      = (const float*)d_in[0];
    const float* h0     = (const float*)d_in[1];
    const float* c0     = (const float*)d_in[2];
    const float* E      = (const float*)d_in[3];
    const float* adj    = (const float*)d_in[4];
    const float* Wg     = (const float*)d_in[5];
    const float* bg     = (const float*)d_in[6];
    const float* Wc     = (const float*)d_in[7];
    const float* bc     = (const float*)d_in[8];
    float* out = (float*)d_out;
    (void)in_sizes; (void)n_in; (void)out_size;

    float *SS, *Wgn, *bgn, *Wcn, *bcn, *XA, *HS, *XIN, *XC, *XG, *XGC, *Z;
    cudaGetSymbolAddress((void**)&SS,  g_SS);
    cudaGetSymbolAddress((void**)&Wgn, g_Wgn);
    cudaGetSymbolAddress((void**)&bgn, g_bgn);
    cudaGetSymbolAddress((void**)&Wcn, g_Wcn);
    cudaGetSymbolAddress((void**)&bcn, g_bcn);
    cudaGetSymbolAddress((void**)&XA,  g_XA);
    cudaGetSymbolAddress((void**)&HS,  g_HS);
    cudaGetSymbolAddress((void**)&XIN, g_XIN);
    cudaGetSymbolAddress((void**)&XC,  g_XC);
    cudaGetSymbolAddress((void**)&XG,  g_XG);
    cudaGetSymbolAddress((void**)&XGC, g_XGC);
    cudaGetSymbolAddress((void**)&Z,   g_Z);

    // ---- supports: SS = [A, 2A^2 - I, adjn, adjn^2] ----
    build_A_kernel   <<<NNODE, 256>>>(E,   SS + 0*NN);
    build_adjn_kernel<<<NNODE, 256>>>(adj, SS + 2*NN);
    dim3 g307((NNODE+127)/128, (NNODE+127)/128);
    sgemm_kernel<<<g307, 256>>>(NNODE, NNODE, NNODE, SS+0*NN, NNODE, SS+0*NN, NNODE, SS+1*NN, NNODE);
    cheb_fix_kernel<<<(NN+255)/256, 256>>>(SS + 1*NN);
    sgemm_kernel<<<g307, 256>>>(NNODE, NNODE, NNODE, SS+2*NN, NNODE, SS+2*NN, NNODE, SS+3*NN, NNODE);

    const int Mg = KR * NNODE;   // 1228 rows for support GEMMs
    for (int l = 0; l < 2; l++) {
        if (l == 0) window_avg_l0_kernel<<<(TNBO+255)/256, 256>>>(x, XA);
        else        window_avg_kernel   <<<(TNBO+255)/256, 256>>>(HS, XA);
        project_Wg_kernel<<<dim3(GK, NNODE), 128>>>(E, Wg, Wgn, l);
        project_bg_kernel<<<NNODE, 128>>>(E, bg, bgn, l);
        project_Wc_kernel<<<dim3(CK, NNODE), 64>>>(E, Wc, Wcn, l);
        project_bc_kernel<<<NNODE, 64>>>(E, bc, bcn, l);
        init_state_kernel<<<(NBO+255)/256, 256>>>(h0, c0, XIN, l);

        for (int t = 0; t < TT; t++) {
            prep_step_kernel<<<(NBO+255)/256, 256>>>(XA, XIN, XC, t);

            // XG = SS @ XIN   (M=1228, N=64*192, K=307)
            dim3 g1((BB*CG)/128, (Mg+127)/128);
            sgemm_kernel<<<g1, 256>>>(Mg, BB*CG, NNODE, SS, NNODE, XIN, BB*CG, XG, BB*CG);

            gate_gemm_kernel<<<NNODE, 256>>>(XG, XIN, Wgn, bgn, Z, XC);

            // XGC = SS @ XC   (M=1228, N=64*128, K=307)
            dim3 g3((BB*CC)/128, (Mg+127)/128);
            sgemm_kernel<<<g3, 256>>>(Mg, BB*CC, NNODE, SS, NNODE, XC, BB*CC, XGC, BB*CC);

            float ca = (float)t / (float)(t + 1);
            float cb = 1.f / (float)(t + 1);
            cand_gemm_kernel<<<NNODE, 256>>>(XGC, XC, Wcn, bcn, Z, XIN,
                                             (l == 1) ? out : HS, t, (l == 1), ca, cb);
        }
    }
}

// round 5
// speedup vs baseline: 1.0915x; 1.0915x over previous
#include <cuda_runtime.h>
#include <cuda_bf16.h>
#include <math.h>

// ---------------------------------------------------------------------------
// AVWDCRNN: adaptive-graph-conv GRU with HiPPO c-state.
// B=64, T=12, N=307, Din=Dout=64, L=2, De=16, K=5 supports.
// Round 5: based byte-for-byte on the PASSING Round-2 kernel (no f32x2 asm —
// implicated in the R3/R4 container failures). Structural change only:
// the second support GEMM no longer recomputes S@x (already in XG ch 0-63);
// it processes just the 64 r*h channels (N 8192 -> 4096, -3.1 GF/step).
// Static scratch shrinks ~25 MB vs R2.
// ---------------------------------------------------------------------------

#define NNODE 307
#define BB    64
#define TT    12
#define DOUT  64
#define DE    16
#define KSUP  5
#define KR    4              // supports actually multiplied (skip identity)
#define CG    192            // gate gconv input channels  [x,h,c]
#define CC    128            // cand gconv input channels  [x,r*h]
#define GK    (KSUP*CG)      // 960
#define CK    (KSUP*CC)      // 640
#define NN    (NNODE*NNODE)
#define NB    (NNODE*BB)
#define NBO   (NB*DOUT)      // 1257472
#define TNBO  (TT*NBO)

// ------------------------------- scratch -----------------------------------
__device__ float g_SS [KR*NN];
__device__ float g_Wgn[NNODE*GK*128];     // per-node gate weights (151 MB)
__device__ float g_bgn[NNODE*128];
__device__ float g_Wcn[NNODE*CK*64];      // per-node cand weights (50 MB)
__device__ float g_bcn[NNODE*64];
__device__ float g_XA [TNBO];             // window-averaged layer input [t][n][b][c]
__device__ float g_HS [TNBO];             // layer-0 hidden outputs [t][n][b][c]
__device__ float g_XIN[NB*CG];            // [n][b][ x | h | c ]
__device__ float g_RH [NB*DOUT];          // [n][b][ r*h ]
__device__ float g_XG [KR*NB*CG];         // S @ XIN (k=1..4); ch 0-63 = S@x
__device__ float g_XGR[KR*NB*DOUT];       // S @ RH  (k=1..4)
__device__ float g_Z  [NB*DOUT];          // update gate z

// ------------------------- supports construction ----------------------------
__global__ void build_A_kernel(const float* __restrict__ E, float* __restrict__ A) {
    __shared__ float row[NNODE];
    __shared__ float er[DE];
    __shared__ float red[256];
    int i = blockIdx.x, tid = threadIdx.x;
    if (tid < DE) er[tid] = E[i*DE + tid];
    __syncthreads();
    for (int j = tid; j < NNODE; j += 256) {
        float s = 0.f;
        #pragma unroll
        for (int d = 0; d < DE; d++) s += er[d] * E[j*DE + d];
        row[j] = fmaxf(s, 0.f);
    }
    __syncthreads();
    float m = -1e30f;
    for (int j = tid; j < NNODE; j += 256) m = fmaxf(m, row[j]);
    red[tid] = m; __syncthreads();
    for (int s = 128; s > 0; s >>= 1) { if (tid < s) red[tid] = fmaxf(red[tid], red[tid+s]); __syncthreads(); }
    m = red[0]; __syncthreads();
    float sum = 0.f;
    for (int j = tid; j < NNODE; j += 256) { float e = expf(row[j]-m); row[j] = e; sum += e; }
    red[tid] = sum; __syncthreads();
    for (int s = 128; s > 0; s >>= 1) { if (tid < s) red[tid] += red[tid+s]; __syncthreads(); }
    float inv = 1.f / red[0];
    for (int j = tid; j < NNODE; j += 256) A[i*NNODE + j] = row[j] * inv;
}

__global__ void build_adjn_kernel(const float* __restrict__ adj, float* __restrict__ out) {
    __shared__ float red[256];
    int i = blockIdx.x, tid = threadIdx.x;
    float sum = 0.f;
    for (int j = tid; j < NNODE; j += 256) sum += adj[i*NNODE + j];
    red[tid] = sum; __syncthreads();
    for (int s = 128; s > 0; s >>= 1) { if (tid < s) red[tid] += red[tid+s]; __syncthreads(); }
    float inv = 1.f / (red[0] + 1e-8f);
    for (int j = tid; j < NNODE; j += 256) out[i*NNODE + j] = adj[i*NNODE + j] * inv;
}

__global__ void cheb_fix_kernel(float* __restrict__ S1) {   // S1 = 2*S1 - I
    int idx = blockIdx.x*blockDim.x + threadIdx.x;
    if (idx >= NN) return;
    float v = 2.f * S1[idx];
    if (idx / NNODE == idx % NNODE) v -= 1.f;
    S1[idx] = v;
}

// ------------------------- generic SGEMM (row-major) ------------------------
__global__ __launch_bounds__(256)
void sgemm_kernel(int M, int N, int K,
                  const float* __restrict__ A, int lda,
                  const float* __restrict__ B, int ldb,
                  float* __restrict__ C, int ldc)
{
    __shared__ float As[8][128];
    __shared__ float Bs[8][128];
    int tid = threadIdx.x;
    int m0 = blockIdx.y * 128;
    int n0 = blockIdx.x * 128;
    int tx = tid % 16, ty = tid / 16;
    float acc[8][8];
    #pragma unroll
    for (int i = 0; i < 8; i++)
        #pragma unroll
        for (int j = 0; j < 8; j++) acc[i][j] = 0.f;

    int arow = tid / 2;          // 0..127
    int acol = (tid % 2) * 4;    // 0 / 4
    int brow = tid / 32;         // 0..7
    int bcol = (tid % 32) * 4;   // 0..124

    for (int kt = 0; kt < K; kt += 8) {
        #pragma unroll
        for (int j = 0; j < 4; j++) {
            int m = m0 + arow, k = kt + acol + j;
            As[acol + j][arow] = (m < M && k < K) ? A[(long long)m*lda + k] : 0.f;
        }
        #pragma unroll
        for (int j = 0; j < 4; j++) {
            int k = kt + brow, n = n0 + bcol + j;
            Bs[brow][bcol + j] = (k < K && n < N) ? B[(long long)k*ldb + n] : 0.f;
        }
        __syncthreads();
        #pragma unroll
        for (int kk = 0; kk < 8; kk++) {
            float a[8], b[8];
            #pragma unroll
            for (int i = 0; i < 4; i++) { a[i] = As[kk][ty*4+i]; a[4+i] = As[kk][64+ty*4+i]; }
            #pragma unroll
            for (int j = 0; j < 4; j++) { b[j] = Bs[kk][tx*4+j]; b[4+j] = Bs[kk][64+tx*4+j]; }
            #pragma unroll
            for (int i = 0; i < 8; i++)
                #pragma unroll
                for (int j = 0; j < 8; j++) acc[i][j] += a[i] * b[j];
        }
        __syncthreads();
    }
    #pragma unroll
    for (int i = 0; i < 8; i++) {
        int m = m0 + (i < 4 ? ty*4+i : 64 + ty*4 + (i-4));
        if (m >= M) continue;
        #pragma unroll
        for (int j = 0; j < 8; j++) {
            int n = n0 + (j < 4 ? tx*4+j : 64 + tx*4 + (j-4));
            if (n < N) C[(long long)m*ldc + n] = acc[i][j];
        }
    }
}

// ---------------------- per-node weight projection --------------------------
__global__ void project_Wg_kernel(const float* __restrict__ E, const float* __restrict__ Wg,
                                  float* __restrict__ Wgn, int l) {
    int kc = blockIdx.x, n = blockIdx.y, o = threadIdx.x;   // grid (960, 307), block 128
    const float* er = E + n*DE;
    float acc = 0.f;
    #pragma unroll
    for (int d = 0; d < DE; d++) acc += er[d] * Wg[((l*DE + d)*GK + kc)*128 + o];
    Wgn[((long long)n*GK + kc)*128 + o] = acc;
}
__global__ void project_Wc_kernel(const float* __restrict__ E, const float* __restrict__ Wc,
                                  float* __restrict__ Wcn, int l) {
    int kc = blockIdx.x, n = blockIdx.y, o = threadIdx.x;   // grid (640, 307), block 64
    const float* er = E + n*DE;
    float acc = 0.f;
    #pragma unroll
    for (int d = 0; d < DE; d++) acc += er[d] * Wc[((l*DE + d)*CK + kc)*64 + o];
    Wcn[((long long)n*CK + kc)*64 + o] = acc;
}
__global__ void project_bg_kernel(const float* __restrict__ E, const float* __restrict__ bg,
                                  float* __restrict__ bgn, int l) {
    int n = blockIdx.x, o = threadIdx.x;
    float acc = 0.f;
    #pragma unroll
    for (int d = 0; d < DE; d++) acc += E[n*DE+d] * bg[(l*DE + d)*128 + o];
    bgn[n*128 + o] = acc;
}
__global__ void project_bc_kernel(const float* __restrict__ E, const float* __restrict__ bc,
                                  float* __restrict__ bcn, int l) {
    int n = blockIdx.x, o = threadIdx.x;
    float acc = 0.f;
    #pragma unroll
    for (int d = 0; d < DE; d++) acc += E[n*DE+d] * bc[(l*DE + d)*64 + o];
    bcn[n*64 + o] = acc;
}

// ----------------------------- data movement --------------------------------
__global__ void window_avg_l0_kernel(const float* __restrict__ x, float* __restrict__ XA) {
    long long idx = (long long)blockIdx.x*blockDim.x + threadIdx.x;   // [t][n][b][c]
    if (idx >= TNBO) return;
    int c = (int)(idx % DOUT);
    int b = (int)((idx / DOUT) % BB);
    int n = (int)((idx / (DOUT*BB)) % NNODE);
    int t = (int)(idx / ((long long)DOUT*BB*NNODE));
    long long base = (((long long)b*TT + t)*NNODE + n)*DOUT + c;
    const long long dT = (long long)NNODE*DOUT;
    float v;
    if (t == 0 || t == TT-1) v = x[base];
    else v = (x[base - dT] + x[base] + x[base + dT]) * (1.f/3.f);
    XA[idx] = v;
}

__global__ void window_avg_kernel(const float* __restrict__ IN, float* __restrict__ XA) {
    int idx = blockIdx.x*blockDim.x + threadIdx.x;   // [t][n][b][c]
    if (idx >= TNBO) return;
    int t = idx / NBO;
    if (t == 0 || t == TT-1) XA[idx] = IN[idx];
    else XA[idx] = (IN[idx-NBO] + IN[idx] + IN[idx+NBO]) * (1.f/3.f);
}

__global__ void init_state_kernel(const float* __restrict__ h0, const float* __restrict__ c0,
                                  float* __restrict__ XIN, int l) {
    int idx = blockIdx.x*blockDim.x + threadIdx.x;   // (n,b,o)
    if (idx >= NBO) return;
    int o = idx % DOUT;
    int b = (idx / DOUT) % BB;
    int n = idx / (DOUT*BB);
    int src = ((l*BB + b)*NNODE + n)*DOUT + o;
    XIN[(n*BB + b)*CG + 64  + o] = h0[src];
    XIN[(n*BB + b)*CG + 128 + o] = c0[src];
}

__global__ void prep_step_kernel(const float* __restrict__ XA, float* __restrict__ XIN, int t) {
    int idx = blockIdx.x*blockDim.x + threadIdx.x;   // (n,b,o)
    if (idx >= NBO) return;
    int o  = idx % DOUT;
    int nb = idx / DOUT;
    XIN[nb*CG + o] = XA[(long long)t*NBO + idx];
}

// ----------------- gate: per-node GEMM + sigmoid + r*h ----------------------
__global__ __launch_bounds__(256)
void gate_gemm_kernel(const float* __restrict__ XG, const float* __restrict__ XIN,
                      const float* __restrict__ Wgn, const float* __restrict__ bgn,
                      float* __restrict__ Z, float* __restrict__ RH)
{
    const int n = blockIdx.x;
    __shared__ float As[16][64];
    __shared__ float Bs[16][128];
    int tid = threadIdx.x;
    int tx = tid % 16, ty = tid / 16;
    float acc[4][8];
    #pragma unroll
    for (int i = 0; i < 4; i++)
        #pragma unroll
        for (int j = 0; j < 8; j++) acc[i][j] = 0.f;

    const float* Wn = Wgn + (long long)n * (GK*128);
    int a_b = tid / 4;           // row b 0..63
    int a_j = (tid % 4) * 4;     // 0,4,8,12

    for (int kt = 0; kt < GK/16; kt++) {
        int kk0  = kt * 16;
        int ksup = kk0 / CG;
        int c0   = kk0 % CG;
        const float* Abase = (ksup == 0)
            ? XIN + (n*BB)*CG + c0
            : XG  + ((((long long)(ksup-1)*NNODE + n)*BB))*CG + c0;
        float4 av = *(const float4*)(Abase + a_b*CG + a_j);
        As[a_j+0][a_b] = av.x; As[a_j+1][a_b] = av.y;
        As[a_j+2][a_b] = av.z; As[a_j+3][a_b] = av.w;
        const float* Bbase = Wn + kk0*128;
        #pragma unroll
        for (int r = 0; r < 2; r++) {
            int f4 = tid + r*256;            // 0..511
            int br = f4 / 32, bc = (f4 % 32) * 4;
            *(float4*)&Bs[br][bc] = *(const float4*)(Bbase + br*128 + bc);
        }
        __syncthreads();
        #pragma unroll
        for (int kk = 0; kk < 16; kk++) {
            float a[4], b[8];
            #pragma unroll
            for (int i = 0; i < 4; i++) a[i] = As[kk][ty*4+i];
            #pragma unroll
            for (int j = 0; j < 4; j++) { b[j] = Bs[kk][tx*4+j]; b[4+j] = Bs[kk][64+tx*4+j]; }
            #pragma unroll
            for (int i = 0; i < 4; i++)
                #pragma unroll
                for (int j = 0; j < 8; j++) acc[i][j] += a[i] * b[j];
        }
        __syncthreads();
    }
    const float* brow = bgn + n*128;
    #pragma unroll
    for (int i = 0; i < 4; i++) {
        int b = ty*4 + i;
        #pragma unroll
        for (int j = 0; j < 8; j++) {
            int o = (j < 4) ? (tx*4 + j) : (64 + tx*4 + (j-4));
            float v = acc[i][j] + brow[o];
            float s = 1.f / (1.f + expf(-v));
            if (o < 64) {
                Z[(n*BB + b)*DOUT + o] = s;                       // z gate
            } else {
                int oo = o - 64;                                  // r gate -> r*h
                float h = XIN[(n*BB + b)*CG + 64 + oo];
                RH[(n*BB + b)*DOUT + oo] = s * h;
            }
        }
    }
}

// --------------- candidate: per-node GEMM + tanh + GRU/HiPPO ----------------
// A channels: c<64  -> x   (k=0: XIN ch 0-63;  k>0: XG ch 0-63  = S@x)
//             c>=64 -> r*h (k=0: RH;           k>0: XGR = S@RH)
__global__ __launch_bounds__(256)
void cand_gemm_kernel(const float* __restrict__ XG, const float* __restrict__ XIN,
                      const float* __restrict__ RH, const float* __restrict__ XGR,
                      const float* __restrict__ Wcn, const float* __restrict__ bcn,
                      const float* __restrict__ Z, float* __restrict__ XINout,
                      float* __restrict__ OUT, int t, int is_final, float ca, float cb)
{
    const int n = blockIdx.x;
    __shared__ float As[16][64];
    __shared__ float Bs[16][64];
    int tid = threadIdx.x;
    int tx = tid % 16, ty = tid / 16;
    float acc[4][4];
    #pragma unroll
    for (int i = 0; i < 4; i++)
        #pragma unroll
        for (int j = 0; j < 4; j++) acc[i][j] = 0.f;

    const float* Wn = Wcn + (long long)n * (CK*64);
    int a_b = tid / 4;
    int a_j = (tid % 4) * 4;

    for (int kt = 0; kt < CK/16; kt++) {
        int kk0  = kt * 16;
        int ksup = kk0 / CC;
        int c0   = kk0 % CC;
        const float* Abase;
        int astride;
        if (c0 < 64) {          // x channels
            if (ksup == 0) { Abase = XIN + (n*BB)*CG + c0;                                   astride = CG; }
            else           { Abase = XG + (((long long)(ksup-1)*NNODE + n)*BB)*CG + c0;       astride = CG; }
        } else {                // r*h channels
            if (ksup == 0) { Abase = RH + (n*BB)*DOUT + (c0 - 64);                            astride = DOUT; }
            else           { Abase = XGR + (((long long)(ksup-1)*NNODE + n)*BB)*DOUT + (c0-64); astride = DOUT; }
        }
        float4 av = *(const float4*)(Abase + a_b*astride + a_j);
        As[a_j+0][a_b] = av.x; As[a_j+1][a_b] = av.y;
        As[a_j+2][a_b] = av.z; As[a_j+3][a_b] = av.w;
        {
            int br = tid / 16, bc = (tid % 16) * 4;      // 16 rows x 64 cols
            *(float4*)&Bs[br][bc] = *(const float4*)(Wn + (kk0 + br)*64 + bc);
        }
        __syncthreads();
        #pragma unroll
        for (int kk = 0; kk < 16; kk++) {
            float a[4], b[4];
            #pragma unroll
            for (int i = 0; i < 4; i++) a[i] = As[kk][ty*4+i];
            #pragma unroll
            for (int j = 0; j < 4; j++) b[j] = Bs[kk][tx*4+j];
            #pragma unroll
            for (int i = 0; i < 4; i++)
                #pragma unroll
                for (int j = 0; j < 4; j++) acc[i][j] += a[i] * b[j];
        }
        __syncthreads();
    }
    const float* brow = bcn + n*64;
    #pragma unroll
    for (int i = 0; i < 4; i++) {
        int b = ty*4 + i;
        #pragma unroll
        for (int j = 0; j < 4; j++) {
            int o = tx*4 + j;
            float hc = tanhf(acc[i][j] + brow[o]);
            float z  = Z[(n*BB + b)*DOUT + o];
            int ih   = (n*BB + b)*CG + 64 + o;
            float h_old = XINout[ih];
            float c_old = XINout[ih + 64];
            float h_new = z*h_old + (1.f - z)*hc;
            float c_new = ca*c_old + cb*h_new;
            XINout[ih]      = h_new;
            XINout[ih + 64] = c_new;
            if (is_final) OUT[(((long long)b*TT + t)*NNODE + n)*DOUT + o] = h_new;   // (B,T,N,O)
            else          OUT[(((long long)t*NNODE + n)*BB + b)*DOUT + o] = h_new;   // [t][n][b][o]
        }
    }
}

// -------------------------------- driver ------------------------------------
extern "C" void kernel_launch(void* const* d_in, const int* in_sizes, int n_in,
                              void* d_out, int out_size)
{
    const float* x   = (const float*)d_in[0];
    const float* h0  = (const float*)d_in[1];
    const float* c0  = (const float*)d_in[2];
    const float* E   = (const float*)d_in[3];
    const float* adj = (const float*)d_in[4];
    const float* Wg  = (const float*)d_in[5];
    const float* bg  = (const float*)d_in[6];
    const float* Wc  = (const float*)d_in[7];
    const float* bc  = (const float*)d_in[8];
    float* out = (float*)d_out;
    (void)in_sizes; (void)n_in; (void)out_size;

    float *SS, *Wgn, *bgn, *Wcn, *bcn, *XA, *HS, *XIN, *RH, *XG, *XGR, *Z;
    cudaGetSymbolAddress((void**)&SS,  g_SS);
    cudaGetSymbolAddress((void**)&Wgn, g_Wgn);
    cudaGetSymbolAddress((void**)&bgn, g_bgn);
    cudaGetSymbolAddress((void**)&Wcn, g_Wcn);
    cudaGetSymbolAddress((void**)&bcn, g_bcn);
    cudaGetSymbolAddress((void**)&XA,  g_XA);
    cudaGetSymbolAddress((void**)&HS,  g_HS);
    cudaGetSymbolAddress((void**)&XIN, g_XIN);
    cudaGetSymbolAddress((void**)&RH,  g_RH);
    cudaGetSymbolAddress((void**)&XG,  g_XG);
    cudaGetSymbolAddress((void**)&XGR, g_XGR);
    cudaGetSymbolAddress((void**)&Z,   g_Z);

    // ---- supports: SS = [A, 2A^2 - I, adjn, adjn^2] ----
    build_A_kernel   <<<NNODE, 256>>>(E,   SS + 0*NN);
    build_adjn_kernel<<<NNODE, 256>>>(adj, SS + 2*NN);
    dim3 g307((NNODE+127)/128, (NNODE+127)/128);
    sgemm_kernel<<<g307, 256>>>(NNODE, NNODE, NNODE, SS+0*NN, NNODE, SS+0*NN, NNODE, SS+1*NN, NNODE);
    cheb_fix_kernel<<<(NN+255)/256, 256>>>(SS + 1*NN);
    sgemm_kernel<<<g307, 256>>>(NNODE, NNODE, NNODE, SS+2*NN, NNODE, SS+2*NN, NNODE, SS+3*NN, NNODE);

    const int Mg = KR * NNODE;   // 1228
    for (int l = 0; l < 2; l++) {
        if (l == 0) window_avg_l0_kernel<<<(TNBO+255)/256, 256>>>(x, XA);
        else        window_avg_kernel   <<<(TNBO+255)/256, 256>>>(HS, XA);
        project_Wg_kernel<<<dim3(GK, NNODE), 128>>>(E, Wg, Wgn, l);
        project_bg_kernel<<<NNODE, 128>>>(E, bg, bgn, l);
        project_Wc_kernel<<<dim3(CK, NNODE), 64>>>(E, Wc, Wcn, l);
        project_bc_kernel<<<NNODE, 64>>>(E, bc, bcn, l);
        init_state_kernel<<<(NBO+255)/256, 256>>>(h0, c0, XIN, l);

        for (int t = 0; t < TT; t++) {
            prep_step_kernel<<<(NBO+255)/256, 256>>>(XA, XIN, t);

            // XG = SS @ XIN   (M=1228, N=64*192, K=307); ch 0-63 = S@x
            dim3 g1((BB*CG)/128, (Mg+127)/128);
            sgemm_kernel<<<g1, 256>>>(Mg, BB*CG, NNODE, SS, NNODE, XIN, BB*CG, XG, BB*CG);

            gate_gemm_kernel<<<NNODE, 256>>>(XG, XIN, Wgn, bgn, Z, RH);

            // XGR = SS @ RH   (M=1228, N=64*64, K=307)  [x-half reused from XG]
            dim3 g3((BB*DOUT)/128, (Mg+127)/128);
            sgemm_kernel<<<g3, 256>>>(Mg, BB*DOUT, NNODE, SS, NNODE, RH, BB*DOUT, XGR, BB*DOUT);

            float ca = (float)t / (float)(t + 1);
            float cb = 1.f / (float)(t + 1);
            cand_gemm_kernel<<<NNODE, 256>>>(XG, XIN, RH, XGR, Wcn, bcn, Z, XIN,
                                             (l == 1) ? out : HS, t, (l == 1), ca, cb);
        }
    }
}

// round 6
// speedup vs baseline: 1.4800x; 1.3560x over previous
#include <cuda_runtime.h>
#include <cuda_bf16.h>
#include <math.h>

// ---------------------------------------------------------------------------
// AVWDCRNN: adaptive-graph-conv GRU with HiPPO c-state.
// B=64, T=12, N=307, Din=Dout=64, L=2, De=16, K=5 supports.
// Round 6: support GEMMs (S@XIN, S@RH — 66% of flops) moved to tensor cores
// via split-bf16 emulated fp32 (C = Sh*Xh + Sh*Xl + Sl*Xh) using classic
// mma.sync.m16n8k16 + ldmatrix (PTX 7.0-era, toolchain-safe). S is split
// hi/lo once per launch; X is split while staging to shared memory.
// Everything else identical to the passing Round-5 kernel.
// ---------------------------------------------------------------------------

#define NNODE 307
#define BB    64
#define TT    12
#define DOUT  64
#define DE    16
#define KSUP  5
#define KR    4
#define CG    192
#define CC    128
#define GK    (KSUP*CG)      // 960
#define CK    (KSUP*CC)      // 640
#define NN    (NNODE*NNODE)
#define NB    (NNODE*BB)
#define NBO   (NB*DOUT)
#define TNBO  (TT*NBO)
#define MG    (KR*NNODE)     // 1228 support-GEMM rows
#define KTPAD 320            // K=307 padded to 10 k-tiles of 32

// ------------------------------- scratch -----------------------------------
__device__ float g_SS [KR*NN];
__device__ __nv_bfloat16 g_Shi[MG*KTPAD];  // split supports (hi)
__device__ __nv_bfloat16 g_Slo[MG*KTPAD];  // split supports (lo)
__device__ float g_Wgn[NNODE*GK*128];
__device__ float g_bgn[NNODE*128];
__device__ float g_Wcn[NNODE*CK*64];
__device__ float g_bcn[NNODE*64];
__device__ float g_XA [TNBO];
__device__ float g_HS [TNBO];
__device__ float g_XIN[NB*CG];
__device__ float g_RH [NB*DOUT];
__device__ float g_XG [KR*NB*CG];
__device__ float g_XGR[KR*NB*DOUT];
__device__ float g_Z  [NB*DOUT];

// --------------------------- mma helpers ------------------------------------
__device__ __forceinline__ void ldsm_x4(unsigned* r, unsigned addr) {
    asm volatile("ldmatrix.sync.aligned.m8n8.x4.shared.b16 {%0,%1,%2,%3}, [%4];"
                 : "=r"(r[0]), "=r"(r[1]), "=r"(r[2]), "=r"(r[3]) : "r"(addr));
}
__device__ __forceinline__ void ldsm_x4t(unsigned* r, unsigned addr) {
    asm volatile("ldmatrix.sync.aligned.m8n8.x4.trans.shared.b16 {%0,%1,%2,%3}, [%4];"
                 : "=r"(r[0]), "=r"(r[1]), "=r"(r[2]), "=r"(r[3]) : "r"(addr));
}
__device__ __forceinline__ void mma16816(float* d, const unsigned* a, const unsigned* b) {
    asm volatile("mma.sync.aligned.m16n8k16.row.col.f32.bf16.bf16.f32 "
                 "{%0,%1,%2,%3},{%4,%5,%6,%7},{%8,%9},{%0,%1,%2,%3};"
                 : "+f"(d[0]), "+f"(d[1]), "+f"(d[2]), "+f"(d[3])
                 : "r"(a[0]), "r"(a[1]), "r"(a[2]), "r"(a[3]), "r"(b[0]), "r"(b[1]));
}

// ------------------------- supports construction ----------------------------
__global__ void build_A_kernel(const float* __restrict__ E, float* __restrict__ A) {
    __shared__ float row[NNODE];
    __shared__ float er[DE];
    __shared__ float red[256];
    int i = blockIdx.x, tid = threadIdx.x;
    if (tid < DE) er[tid] = E[i*DE + tid];
    __syncthreads();
    for (int j = tid; j < NNODE; j += 256) {
        float s = 0.f;
        #pragma unroll
        for (int d = 0; d < DE; d++) s += er[d] * E[j*DE + d];
        row[j] = fmaxf(s, 0.f);
    }
    __syncthreads();
    float m = -1e30f;
    for (int j = tid; j < NNODE; j += 256) m = fmaxf(m, row[j]);
    red[tid] = m; __syncthreads();
    for (int s = 128; s > 0; s >>= 1) { if (tid < s) red[tid] = fmaxf(red[tid], red[tid+s]); __syncthreads(); }
    m = red[0]; __syncthreads();
    float sum = 0.f;
    for (int j = tid; j < NNODE; j += 256) { float e = expf(row[j]-m); row[j] = e; sum += e; }
    red[tid] = sum; __syncthreads();
    for (int s = 128; s > 0; s >>= 1) { if (tid < s) red[tid] += red[tid+s]; __syncthreads(); }
    float inv = 1.f / red[0];
    for (int j = tid; j < NNODE; j += 256) A[i*NNODE + j] = row[j] * inv;
}

__global__ void build_adjn_kernel(const float* __restrict__ adj, float* __restrict__ out) {
    __shared__ float red[256];
    int i = blockIdx.x, tid = threadIdx.x;
    float sum = 0.f;
    for (int j = tid; j < NNODE; j += 256) sum += adj[i*NNODE + j];
    red[tid] = sum; __syncthreads();
    for (int s = 128; s > 0; s >>= 1) { if (tid < s) red[tid] += red[tid+s]; __syncthreads(); }
    float inv = 1.f / (red[0] + 1e-8f);
    for (int j = tid; j < NNODE; j += 256) out[i*NNODE + j] = adj[i*NNODE + j] * inv;
}

__global__ void cheb_fix_kernel(float* __restrict__ S1) {
    int idx = blockIdx.x*blockDim.x + threadIdx.x;
    if (idx >= NN) return;
    float v = 2.f * S1[idx];
    if (idx / NNODE == idx % NNODE) v -= 1.f;
    S1[idx] = v;
}

// Split SS (1228x307 row-major) into bf16 hi/lo, K-padded to 320 with zeros.
__global__ void split_S_kernel(const float* __restrict__ SS,
                               __nv_bfloat16* __restrict__ Shi,
                               __nv_bfloat16* __restrict__ Slo) {
    int idx = blockIdx.x*blockDim.x + threadIdx.x;
    if (idx >= MG*KTPAD) return;
    int m = idx / KTPAD, k = idx % KTPAD;
    float v = (k < NNODE) ? SS[m*NNODE + k] : 0.f;
    __nv_bfloat16 h = __float2bfloat16(v);
    float r = v - __bfloat162float(h);
    Shi[idx] = h;
    Slo[idx] = __float2bfloat16(r);
}

// ------------------------- generic SGEMM (row-major) ------------------------
__global__ __launch_bounds__(256)
void sgemm_kernel(int M, int N, int K,
                  const float* __restrict__ A, int lda,
                  const float* __restrict__ B, int ldb,
                  float* __restrict__ C, int ldc)
{
    __shared__ float As[8][128];
    __shared__ float Bs[8][128];
    int tid = threadIdx.x;
    int m0 = blockIdx.y * 128;
    int n0 = blockIdx.x * 128;
    int tx = tid % 16, ty = tid / 16;
    float acc[8][8];
    #pragma unroll
    for (int i = 0; i < 8; i++)
        #pragma unroll
        for (int j = 0; j < 8; j++) acc[i][j] = 0.f;

    int arow = tid / 2;
    int acol = (tid % 2) * 4;
    int brow = tid / 32;
    int bcol = (tid % 32) * 4;

    for (int kt = 0; kt < K; kt += 8) {
        #pragma unroll
        for (int j = 0; j < 4; j++) {
            int m = m0 + arow, k = kt + acol + j;
            As[acol + j][arow] = (m < M && k < K) ? A[(long long)m*lda + k] : 0.f;
        }
        #pragma unroll
        for (int j = 0; j < 4; j++) {
            int k = kt + brow, n = n0 + bcol + j;
            Bs[brow][bcol + j] = (k < K && n < N) ? B[(long long)k*ldb + n] : 0.f;
        }
        __syncthreads();
        #pragma unroll
        for (int kk = 0; kk < 8; kk++) {
            float a[8], b[8];
            #pragma unroll
            for (int i = 0; i < 4; i++) { a[i] = As[kk][ty*4+i]; a[4+i] = As[kk][64+ty*4+i]; }
            #pragma unroll
            for (int j = 0; j < 4; j++) { b[j] = Bs[kk][tx*4+j]; b[4+j] = Bs[kk][64+tx*4+j]; }
            #pragma unroll
            for (int i = 0; i < 8; i++)
                #pragma unroll
                for (int j = 0; j < 8; j++) acc[i][j] += a[i] * b[j];
        }
        __syncthreads();
    }
    #pragma unroll
    for (int i = 0; i < 8; i++) {
        int m = m0 + (i < 4 ? ty*4+i : 64 + ty*4 + (i-4));
        if (m >= M) continue;
        #pragma unroll
        for (int j = 0; j < 8; j++) {
            int n = n0 + (j < 4 ? tx*4+j : 64 + tx*4 + (j-4));
            if (n < N) C[(long long)m*ldc + n] = acc[i][j];
        }
    }
}

// --------------- tensor-core support GEMM: C = S @ B (split bf16) -----------
// A: Shi/Slo [MG][KTPAD] bf16. B: fp32 [307][ldb]. C: fp32 [MG][ldc].
// N must be a multiple of 128. Block 128x128, k-tile 32, 8 warps of 64x32.
__global__ __launch_bounds__(256)
void tgemm_kernel(int M, int N,
                  const __nv_bfloat16* __restrict__ Ah,
                  const __nv_bfloat16* __restrict__ Al,
                  const float* __restrict__ B, int ldb,
                  float* __restrict__ C, int ldc)
{
    __shared__ __nv_bfloat16 sAh[128][40];
    __shared__ __nv_bfloat16 sAl[128][40];
    __shared__ __nv_bfloat16 sBh[32][136];
    __shared__ __nv_bfloat16 sBl[32][136];

    int tid  = threadIdx.x;
    int warp = tid >> 5, lane = tid & 31;
    int m0 = blockIdx.y * 128, n0 = blockIdx.x * 128;
    int wm = (warp >> 2) * 64, wn = (warp & 3) * 32;

    float acc[4][4][4];
    #pragma unroll
    for (int i = 0; i < 4; i++)
        #pragma unroll
        for (int j = 0; j < 4; j++)
            #pragma unroll
            for (int q = 0; q < 4; q++) acc[i][j][q] = 0.f;

    int ar = tid >> 1, ac = (tid & 1) * 16;     // A loader: row, col-half
    int bk = tid >> 3, bn = (tid & 7) * 16;     // B loader: k-row, n-chunk

    for (int kt = 0; kt < KTPAD/32; kt++) {
        // stage A (both splits), zeros for out-of-range rows
        {
            bool mok = (m0 + ar) < M;
            const __nv_bfloat16* gh = Ah + (long long)(m0 + ar)*KTPAD + kt*32 + ac;
            const __nv_bfloat16* gl = Al + (long long)(m0 + ar)*KTPAD + kt*32 + ac;
            #pragma unroll
            for (int j = 0; j < 16; j += 2) {
                unsigned vh = mok ? *(const unsigned*)(gh + j) : 0u;
                unsigned vl = mok ? *(const unsigned*)(gl + j) : 0u;
                *(unsigned*)&sAh[ar][ac + j] = vh;
                *(unsigned*)&sAl[ar][ac + j] = vl;
            }
        }
        // stage B with on-the-fly hi/lo split
        {
            int kg = kt*32 + bk;
            if (kg < NNODE) {
                const float* gb = B + (long long)kg*ldb + n0 + bn;
                #pragma unroll
                for (int j = 0; j < 16; j += 4) {
                    float4 v = *(const float4*)(gb + j);
                    __nv_bfloat16 h0 = __float2bfloat16(v.x);
                    __nv_bfloat16 h1 = __float2bfloat16(v.y);
                    __nv_bfloat16 h2 = __float2bfloat16(v.z);
                    __nv_bfloat16 h3 = __float2bfloat16(v.w);
                    __nv_bfloat16 l0 = __float2bfloat16(v.x - __bfloat162float(h0));
                    __nv_bfloat16 l1 = __float2bfloat16(v.y - __bfloat162float(h1));
                    __nv_bfloat16 l2 = __float2bfloat16(v.z - __bfloat162float(h2));
                    __nv_bfloat16 l3 = __float2bfloat16(v.w - __bfloat162float(h3));
                    *(__nv_bfloat162*)&sBh[bk][bn + j]     = __halves2bfloat162(h0, h1);
                    *(__nv_bfloat162*)&sBh[bk][bn + j + 2] = __halves2bfloat162(h2, h3);
                    *(__nv_bfloat162*)&sBl[bk][bn + j]     = __halves2bfloat162(l0, l1);
                    *(__nv_bfloat162*)&sBl[bk][bn + j + 2] = __halves2bfloat162(l2, l3);
                }
            } else {
                #pragma unroll
                for (int j = 0; j < 16; j += 2) {
                    *(unsigned*)&sBh[bk][bn + j] = 0u;
                    *(unsigned*)&sBl[bk][bn + j] = 0u;
                }
            }
        }
        __syncthreads();

        #pragma unroll
        for (int ks = 0; ks < 2; ks++) {
            unsigned afh[4][4], afl[4][4], bfh[4][2], bfl[4][2];
            #pragma unroll
            for (int mi = 0; mi < 4; mi++) {
                int row = wm + mi*16 + (lane & 15);
                int col = ks*16 + (lane >> 4) * 8;
                ldsm_x4(afh[mi], (unsigned)__cvta_generic_to_shared(&sAh[row][col]));
                ldsm_x4(afl[mi], (unsigned)__cvta_generic_to_shared(&sAl[row][col]));
            }
            #pragma unroll
            for (int np = 0; np < 2; np++) {
                int k  = ks*16 + (lane & 15);
                int nn = wn + np*16 + (lane >> 4) * 8;
                unsigned r[4];
                ldsm_x4t(r, (unsigned)__cvta_generic_to_shared(&sBh[k][nn]));
                bfh[np*2][0] = r[0]; bfh[np*2][1] = r[1];
                bfh[np*2+1][0] = r[2]; bfh[np*2+1][1] = r[3];
                ldsm_x4t(r, (unsigned)__cvta_generic_to_shared(&sBl[k][nn]));
                bfl[np*2][0] = r[0]; bfl[np*2][1] = r[1];
                bfl[np*2+1][0] = r[2]; bfl[np*2+1][1] = r[3];
            }
            #pragma unroll
            for (int mi = 0; mi < 4; mi++)
                #pragma unroll
                for (int ni = 0; ni < 4; ni++) {
                    mma16816(acc[mi][ni], afh[mi], bfh[ni]);
                    mma16816(acc[mi][ni], afh[mi], bfl[ni]);
                    mma16816(acc[mi][ni], afl[mi], bfh[ni]);
                }
        }
        __syncthreads();
    }

    // store
    int g = lane >> 2, tq = lane & 3;
    #pragma unroll
    for (int mi = 0; mi < 4; mi++) {
        #pragma unroll
        for (int ni = 0; ni < 4; ni++) {
            int row = m0 + wm + mi*16 + g;
            int col = n0 + wn + ni*8 + tq*2;
            if (row < M)
                *(float2*)&C[(long long)row*ldc + col] =
                    make_float2(acc[mi][ni][0], acc[mi][ni][1]);
            if (row + 8 < M)
                *(float2*)&C[(long long)(row+8)*ldc + col] =
                    make_float2(acc[mi][ni][2], acc[mi][ni][3]);
        }
    }
}

// ---------------------- per-node weight projection --------------------------
__global__ void project_Wg_kernel(const float* __restrict__ E, const float* __restrict__ Wg,
                                  float* __restrict__ Wgn, int l) {
    int kc = blockIdx.x, n = blockIdx.y, o = threadIdx.x;
    const float* er = E + n*DE;
    float acc = 0.f;
    #pragma unroll
    for (int d = 0; d < DE; d++) acc += er[d] * Wg[((l*DE + d)*GK + kc)*128 + o];
    Wgn[((long long)n*GK + kc)*128 + o] = acc;
}
__global__ void project_Wc_kernel(const float* __restrict__ E, const float* __restrict__ Wc,
                                  float* __restrict__ Wcn, int l) {
    int kc = blockIdx.x, n = blockIdx.y, o = threadIdx.x;
    const float* er = E + n*DE;
    float acc = 0.f;
    #pragma unroll
    for (int d = 0; d < DE; d++) acc += er[d] * Wc[((l*DE + d)*CK + kc)*64 + o];
    Wcn[((long long)n*CK + kc)*64 + o] = acc;
}
__global__ void project_bg_kernel(const float* __restrict__ E, const float* __restrict__ bg,
                                  float* __restrict__ bgn, int l) {
    int n = blockIdx.x, o = threadIdx.x;
    float acc = 0.f;
    #pragma unroll
    for (int d = 0; d < DE; d++) acc += E[n*DE+d] * bg[(l*DE + d)*128 + o];
    bgn[n*128 + o] = acc;
}
__global__ void project_bc_kernel(const float* __restrict__ E, const float* __restrict__ bc,
                                  float* __restrict__ bcn, int l) {
    int n = blockIdx.x, o = threadIdx.x;
    float acc = 0.f;
    #pragma unroll
    for (int d = 0; d < DE; d++) acc += E[n*DE+d] * bc[(l*DE + d)*64 + o];
    bcn[n*64 + o] = acc;
}

// ----------------------------- data movement --------------------------------
__global__ void window_avg_l0_kernel(const float* __restrict__ x, float* __restrict__ XA) {
    long long idx = (long long)blockIdx.x*blockDim.x + threadIdx.x;
    if (idx >= TNBO) return;
    int c = (int)(idx % DOUT);
    int b = (int)((idx / DOUT) % BB);
    int n = (int)((idx / (DOUT*BB)) % NNODE);
    int t = (int)(idx / ((long long)DOUT*BB*NNODE));
    long long base = (((long long)b*TT + t)*NNODE + n)*DOUT + c;
    const long long dT = (long long)NNODE*DOUT;
    float v;
    if (t == 0 || t == TT-1) v = x[base];
    else v = (x[base - dT] + x[base] + x[base + dT]) * (1.f/3.f);
    XA[idx] = v;
}

__global__ void window_avg_kernel(const float* __restrict__ IN, float* __restrict__ XA) {
    int idx = blockIdx.x*blockDim.x + threadIdx.x;
    if (idx >= TNBO) return;
    int t = idx / NBO;
    if (t == 0 || t == TT-1) XA[idx] = IN[idx];
    else XA[idx] = (IN[idx-NBO] + IN[idx] + IN[idx+NBO]) * (1.f/3.f);
}

__global__ void init_state_kernel(const float* __restrict__ h0, const float* __restrict__ c0,
                                  float* __restrict__ XIN, int l) {
    int idx = blockIdx.x*blockDim.x + threadIdx.x;
    if (idx >= NBO) return;
    int o = idx % DOUT;
    int b = (idx / DOUT) % BB;
    int n = idx / (DOUT*BB);
    int src = ((l*BB + b)*NNODE + n)*DOUT + o;
    XIN[(n*BB + b)*CG + 64  + o] = h0[src];
    XIN[(n*BB + b)*CG + 128 + o] = c0[src];
}

__global__ void prep_step_kernel(const float* __restrict__ XA, float* __restrict__ XIN, int t) {
    int idx = blockIdx.x*blockDim.x + threadIdx.x;
    if (idx >= NBO) return;
    int o  = idx % DOUT;
    int nb = idx / DOUT;
    XIN[nb*CG + o] = XA[(long long)t*NBO + idx];
}

// ----------------- gate: per-node GEMM + sigmoid + r*h ----------------------
__global__ __launch_bounds__(256)
void gate_gemm_kernel(const float* __restrict__ XG, const float* __restrict__ XIN,
                      const float* __restrict__ Wgn, const float* __restrict__ bgn,
                      float* __restrict__ Z, float* __restrict__ RH)
{
    const int n = blockIdx.x;
    __shared__ float As[16][64];
    __shared__ float Bs[16][128];
    int tid = threadIdx.x;
    int tx = tid % 16, ty = tid / 16;
    float acc[4][8];
    #pragma unroll
    for (int i = 0; i < 4; i++)
        #pragma unroll
        for (int j = 0; j < 8; j++) acc[i][j] = 0.f;

    const float* Wn = Wgn + (long long)n * (GK*128);
    int a_b = tid / 4;
    int a_j = (tid % 4) * 4;

    for (int kt = 0; kt < GK/16; kt++) {
        int kk0  = kt * 16;
        int ksup = kk0 / CG;
        int c0   = kk0 % CG;
        const float* Abase = (ksup == 0)
            ? XIN + (n*BB)*CG + c0
            : XG  + ((((long long)(ksup-1)*NNODE + n)*BB))*CG + c0;
        float4 av = *(const float4*)(Abase + a_b*CG + a_j);
        As[a_j+0][a_b] = av.x; As[a_j+1][a_b] = av.y;
        As[a_j+2][a_b] = av.z; As[a_j+3][a_b] = av.w;
        const float* Bbase = Wn + kk0*128;
        #pragma unroll
        for (int r = 0; r < 2; r++) {
            int f4 = tid + r*256;
            int br = f4 / 32, bc = (f4 % 32) * 4;
            *(float4*)&Bs[br][bc] = *(const float4*)(Bbase + br*128 + bc);
        }
        __syncthreads();
        #pragma unroll
        for (int kk = 0; kk < 16; kk++) {
            float a[4], b[8];
            #pragma unroll
            for (int i = 0; i < 4; i++) a[i] = As[kk][ty*4+i];
            #pragma unroll
            for (int j = 0; j < 4; j++) { b[j] = Bs[kk][tx*4+j]; b[4+j] = Bs[kk][64+tx*4+j]; }
            #pragma unroll
            for (int i = 0; i < 4; i++)
                #pragma unroll
                for (int j = 0; j < 8; j++) acc[i][j] += a[i] * b[j];
        }
        __syncthreads();
    }
    const float* brow = bgn + n*128;
    #pragma unroll
    for (int i = 0; i < 4; i++) {
        int b = ty*4 + i;
        #pragma unroll
        for (int j = 0; j < 8; j++) {
            int o = (j < 4) ? (tx*4 + j) : (64 + tx*4 + (j-4));
            float v = acc[i][j] + brow[o];
            float s = 1.f / (1.f + expf(-v));
            if (o < 64) {
                Z[(n*BB + b)*DOUT + o] = s;
            } else {
                int oo = o - 64;
                float h = XIN[(n*BB + b)*CG + 64 + oo];
                RH[(n*BB + b)*DOUT + oo] = s * h;
            }
        }
    }
}

// --------------- candidate: per-node GEMM + tanh + GRU/HiPPO ----------------
__global__ __launch_bounds__(256)
void cand_gemm_kernel(const float* __restrict__ XG, const float* __restrict__ XIN,
                      const float* __restrict__ RH, const float* __restrict__ XGR,
                      const float* __restrict__ Wcn, const float* __restrict__ bcn,
                      const float* __restrict__ Z, float* __restrict__ XINout,
                      float* __restrict__ OUT, int t, int is_final, float ca, float cb)
{
    const int n = blockIdx.x;
    __shared__ float As[16][64];
    __shared__ float Bs[16][64];
    int tid = threadIdx.x;
    int tx = tid % 16, ty = tid / 16;
    float acc[4][4];
    #pragma unroll
    for (int i = 0; i < 4; i++)
        #pragma unroll
        for (int j = 0; j < 4; j++) acc[i][j] = 0.f;

    const float* Wn = Wcn + (long long)n * (CK*64);
    int a_b = tid / 4;
    int a_j = (tid % 4) * 4;

    for (int kt = 0; kt < CK/16; kt++) {
        int kk0  = kt * 16;
        int ksup = kk0 / CC;
        int c0   = kk0 % CC;
        const float* Abase;
        int astride;
        if (c0 < 64) {
            if (ksup == 0) { Abase = XIN + (n*BB)*CG + c0;                                    astride = CG; }
            else           { Abase = XG + (((long long)(ksup-1)*NNODE + n)*BB)*CG + c0;        astride = CG; }
        } else {
            if (ksup == 0) { Abase = RH + (n*BB)*DOUT + (c0 - 64);                             astride = DOUT; }
            else           { Abase = XGR + (((long long)(ksup-1)*NNODE + n)*BB)*DOUT + (c0-64); astride = DOUT; }
        }
        float4 av = *(const float4*)(Abase + a_b*astride + a_j);
        As[a_j+0][a_b] = av.x; As[a_j+1][a_b] = av.y;
        As[a_j+2][a_b] = av.z; As[a_j+3][a_b] = av.w;
        {
            int br = tid / 16, bc = (tid % 16) * 4;
            *(float4*)&Bs[br][bc] = *(const float4*)(Wn + (kk0 + br)*64 + bc);
        }
        __syncthreads();
        #pragma unroll
        for (int kk = 0; kk < 16; kk++) {
            float a[4], b[4];
            #pragma unroll
            for (int i = 0; i < 4; i++) a[i] = As[kk][ty*4+i];
            #pragma unroll
            for (int j = 0; j < 4; j++) b[j] = Bs[kk][tx*4+j];
            #pragma unroll
            for (int i = 0; i < 4; i++)
                #pragma unroll
                for (int j = 0; j < 4; j++) acc[i][j] += a[i] * b[j];
        }
        __syncthreads();
    }
    const float* brow = bcn + n*64;
    #pragma unroll
    for (int i = 0; i < 4; i++) {
        int b = ty*4 + i;
        #pragma unroll
        for (int j = 0; j < 4; j++) {
            int o = tx*4 + j;
            float hc = tanhf(acc[i][j] + brow[o]);
            float z  = Z[(n*BB + b)*DOUT + o];
            int ih   = (n*BB + b)*CG + 64 + o;
            float h_old = XINout[ih];
            float c_old = XINout[ih + 64];
            float h_new = z*h_old + (1.f - z)*hc;
            float c_new = ca*c_old + cb*h_new;
            XINout[ih]      = h_new;
            XINout[ih + 64] = c_new;
            if (is_final) OUT[(((long long)b*TT + t)*NNODE + n)*DOUT + o] = h_new;
            else          OUT[(((long long)t*NNODE + n)*BB + b)*DOUT + o] = h_new;
        }
    }
}

// -------------------------------- driver ------------------------------------
extern "C" void kernel_launch(void* const* d_in, const int* in_sizes, int n_in,
                              void* d_out, int out_size)
{
    const float* x   = (const float*)d_in[0];
    const float* h0  = (const float*)d_in[1];
    const float* c0  = (const float*)d_in[2];
    const float* E   = (const float*)d_in[3];
    const float* adj = (const float*)d_in[4];
    const float* Wg  = (const float*)d_in[5];
    const float* bg  = (const float*)d_in[6];
    const float* Wc  = (const float*)d_in[7];
    const float* bc  = (const float*)d_in[8];
    float* out = (float*)d_out;
    (void)in_sizes; (void)n_in; (void)out_size;

    float *SS, *Wgn, *bgn, *Wcn, *bcn, *XA, *HS, *XIN, *RH, *XG, *XGR, *Z;
    __nv_bfloat16 *Shi, *Slo;
    cudaGetSymbolAddress((void**)&SS,  g_SS);
    cudaGetSymbolAddress((void**)&Shi, g_Shi);
    cudaGetSymbolAddress((void**)&Slo, g_Slo);
    cudaGetSymbolAddress((void**)&Wgn, g_Wgn);
    cudaGetSymbolAddress((void**)&bgn, g_bgn);
    cudaGetSymbolAddress((void**)&Wcn, g_Wcn);
    cudaGetSymbolAddress((void**)&bcn, g_bcn);
    cudaGetSymbolAddress((void**)&XA,  g_XA);
    cudaGetSymbolAddress((void**)&HS,  g_HS);
    cudaGetSymbolAddress((void**)&XIN, g_XIN);
    cudaGetSymbolAddress((void**)&RH,  g_RH);
    cudaGetSymbolAddress((void**)&XG,  g_XG);
    cudaGetSymbolAddress((void**)&XGR, g_XGR);
    cudaGetSymbolAddress((void**)&Z,   g_Z);

    // ---- supports: SS = [A, 2A^2 - I, adjn, adjn^2] ----
    build_A_kernel   <<<NNODE, 256>>>(E,   SS + 0*NN);
    build_adjn_kernel<<<NNODE, 256>>>(adj, SS + 2*NN);
    dim3 g307((NNODE+127)/128, (NNODE+127)/128);
    sgemm_kernel<<<g307, 256>>>(NNODE, NNODE, NNODE, SS+0*NN, NNODE, SS+0*NN, NNODE, SS+1*NN, NNODE);
    cheb_fix_kernel<<<(NN+255)/256, 256>>>(SS + 1*NN);
    sgemm_kernel<<<g307, 256>>>(NNODE, NNODE, NNODE, SS+2*NN, NNODE, SS+2*NN, NNODE, SS+3*NN, NNODE);

    // split supports into bf16 hi/lo for the tensor path
    split_S_kernel<<<(MG*KTPAD + 255)/256, 256>>>(SS, Shi, Slo);

    for (int l = 0; l < 2; l++) {
        if (l == 0) window_avg_l0_kernel<<<(TNBO+255)/256, 256>>>(x, XA);
        else        window_avg_kernel   <<<(TNBO+255)/256, 256>>>(HS, XA);
        project_Wg_kernel<<<dim3(GK, NNODE), 128>>>(E, Wg, Wgn, l);
        project_bg_kernel<<<NNODE, 128>>>(E, bg, bgn, l);
        project_Wc_kernel<<<dim3(CK, NNODE), 64>>>(E, Wc, Wcn, l);
        project_bc_kernel<<<NNODE, 64>>>(E, bc, bcn, l);
        init_state_kernel<<<(NBO+255)/256, 256>>>(h0, c0, XIN, l);

        for (int t = 0; t < TT; t++) {
            prep_step_kernel<<<(NBO+255)/256, 256>>>(XA, XIN, t);

            // XG = S @ XIN  (M=1228, N=12288, K=307) — tensor path
            dim3 g1((BB*CG)/128, (MG+127)/128);
            tgemm_kernel<<<g1, 256>>>(MG, BB*CG, Shi, Slo, XIN, BB*CG, XG, BB*CG);

            gate_gemm_kernel<<<NNODE, 256>>>(XG, XIN, Wgn, bgn, Z, RH);

            // XGR = S @ RH  (M=1228, N=4096, K=307) — tensor path
            dim3 g3((BB*DOUT)/128, (MG+127)/128);
            tgemm_kernel<<<g3, 256>>>(MG, BB*DOUT, Shi, Slo, RH, BB*DOUT, XGR, BB*DOUT);

            float ca = (float)t / (float)(t + 1);
            float cb = 1.f / (float)(t + 1);
            cand_gemm_kernel<<<NNODE, 256>>>(XG, XIN, RH, XGR, Wcn, bcn, Z, XIN,
                                             (l == 1) ? out : HS, t, (l == 1), ca, cb);
        }
    }
}

// round 7
// speedup vs baseline: 1.8149x; 1.2263x over previous
#include <cuda_runtime.h>
#include <cuda_bf16.h>
#include <math.h>

// ---------------------------------------------------------------------------
// AVWDCRNN: adaptive-graph-conv GRU with HiPPO c-state.
// B=64, T=12, N=307, Din=Dout=64, L=2, De=16, K=5 supports.
// Round 7: per-node gate/cand GEMMs moved to tensor cores with the same
// split-bf16 scheme proven in Round 6 (C = AhWh + AhWl + AlWh). Projected
// per-node weights are stored directly as bf16 hi/lo (same bytes as fp32).
// Support GEMMs (tgemm) unchanged from Round 6.
// ---------------------------------------------------------------------------

#define NNODE 307
#define BB    64
#define TT    12
#define DOUT  64
#define DE    16
#define KSUP  5
#define KR    4
#define CG    192
#define CC    128
#define GK    (KSUP*CG)      // 960
#define CK    (KSUP*CC)      // 640
#define NN    (NNODE*NNODE)
#define NB    (NNODE*BB)
#define NBO   (NB*DOUT)
#define TNBO  (TT*NBO)
#define MG    (KR*NNODE)     // 1228
#define KTPAD 320

// ------------------------------- scratch -----------------------------------
__device__ float g_SS [KR*NN];
__device__ __nv_bfloat16 g_Shi[MG*KTPAD];
__device__ __nv_bfloat16 g_Slo[MG*KTPAD];
__device__ __nv_bfloat16 g_Wgh[NNODE*GK*128];   // per-node gate weights hi
__device__ __nv_bfloat16 g_Wgl[NNODE*GK*128];   // per-node gate weights lo
__device__ float g_bgn[NNODE*128];
__device__ __nv_bfloat16 g_Wch[NNODE*CK*64];    // per-node cand weights hi
__device__ __nv_bfloat16 g_Wcl[NNODE*CK*64];    // per-node cand weights lo
__device__ float g_bcn[NNODE*64];
__device__ float g_XA [TNBO];
__device__ float g_HS [TNBO];
__device__ float g_XIN[NB*CG];
__device__ float g_RH [NB*DOUT];
__device__ float g_XG [KR*NB*CG];
__device__ float g_XGR[KR*NB*DOUT];
__device__ float g_Z  [NB*DOUT];

// --------------------------- mma helpers ------------------------------------
__device__ __forceinline__ void ldsm_x4(unsigned* r, unsigned addr) {
    asm volatile("ldmatrix.sync.aligned.m8n8.x4.shared.b16 {%0,%1,%2,%3}, [%4];"
                 : "=r"(r[0]), "=r"(r[1]), "=r"(r[2]), "=r"(r[3]) : "r"(addr));
}
__device__ __forceinline__ void ldsm_x4t(unsigned* r, unsigned addr) {
    asm volatile("ldmatrix.sync.aligned.m8n8.x4.trans.shared.b16 {%0,%1,%2,%3}, [%4];"
                 : "=r"(r[0]), "=r"(r[1]), "=r"(r[2]), "=r"(r[3]) : "r"(addr));
}
__device__ __forceinline__ void mma16816(float* d, const unsigned* a, const unsigned* b) {
    asm volatile("mma.sync.aligned.m16n8k16.row.col.f32.bf16.bf16.f32 "
                 "{%0,%1,%2,%3},{%4,%5,%6,%7},{%8,%9},{%0,%1,%2,%3};"
                 : "+f"(d[0]), "+f"(d[1]), "+f"(d[2]), "+f"(d[3])
                 : "r"(a[0]), "r"(a[1]), "r"(a[2]), "r"(a[3]), "r"(b[0]), "r"(b[1]));
}
__device__ __forceinline__ void split2(float x, float y, __nv_bfloat162* hi, __nv_bfloat162* lo) {
    __nv_bfloat16 h0 = __float2bfloat16(x), h1 = __float2bfloat16(y);
    *hi = __halves2bfloat162(h0, h1);
    *lo = __halves2bfloat162(__float2bfloat16(x - __bfloat162float(h0)),
                             __float2bfloat16(y - __bfloat162float(h1)));
}

// ------------------------- supports construction ----------------------------
__global__ void build_A_kernel(const float* __restrict__ E, float* __restrict__ A) {
    __shared__ float row[NNODE];
    __shared__ float er[DE];
    __shared__ float red[256];
    int i = blockIdx.x, tid = threadIdx.x;
    if (tid < DE) er[tid] = E[i*DE + tid];
    __syncthreads();
    for (int j = tid; j < NNODE; j += 256) {
        float s = 0.f;
        #pragma unroll
        for (int d = 0; d < DE; d++) s += er[d] * E[j*DE + d];
        row[j] = fmaxf(s, 0.f);
    }
    __syncthreads();
    float m = -1e30f;
    for (int j = tid; j < NNODE; j += 256) m = fmaxf(m, row[j]);
    red[tid] = m; __syncthreads();
    for (int s = 128; s > 0; s >>= 1) { if (tid < s) red[tid] = fmaxf(red[tid], red[tid+s]); __syncthreads(); }
    m = red[0]; __syncthreads();
    float sum = 0.f;
    for (int j = tid; j < NNODE; j += 256) { float e = expf(row[j]-m); row[j] = e; sum += e; }
    red[tid] = sum; __syncthreads();
    for (int s = 128; s > 0; s >>= 1) { if (tid < s) red[tid] += red[tid+s]; __syncthreads(); }
    float inv = 1.f / red[0];
    for (int j = tid; j < NNODE; j += 256) A[i*NNODE + j] = row[j] * inv;
}

__global__ void build_adjn_kernel(const float* __restrict__ adj, float* __restrict__ out) {
    __shared__ float red[256];
    int i = blockIdx.x, tid = threadIdx.x;
    float sum = 0.f;
    for (int j = tid; j < NNODE; j += 256) sum += adj[i*NNODE + j];
    red[tid] = sum; __syncthreads();
    for (int s = 128; s > 0; s >>= 1) { if (tid < s) red[tid] += red[tid+s]; __syncthreads(); }
    float inv = 1.f / (red[0] + 1e-8f);
    for (int j = tid; j < NNODE; j += 256) out[i*NNODE + j] = adj[i*NNODE + j] * inv;
}

__global__ void cheb_fix_kernel(float* __restrict__ S1) {
    int idx = blockIdx.x*blockDim.x + threadIdx.x;
    if (idx >= NN) return;
    float v = 2.f * S1[idx];
    if (idx / NNODE == idx % NNODE) v -= 1.f;
    S1[idx] = v;
}

__global__ void split_S_kernel(const float* __restrict__ SS,
                               __nv_bfloat16* __restrict__ Shi,
                               __nv_bfloat16* __restrict__ Slo) {
    int idx = blockIdx.x*blockDim.x + threadIdx.x;
    if (idx >= MG*KTPAD) return;
    int m = idx / KTPAD, k = idx % KTPAD;
    float v = (k < NNODE) ? SS[m*NNODE + k] : 0.f;
    __nv_bfloat16 h = __float2bfloat16(v);
    Shi[idx] = h;
    Slo[idx] = __float2bfloat16(v - __bfloat162float(h));
}

// ------------------------- generic SGEMM (row-major) ------------------------
__global__ __launch_bounds__(256)
void sgemm_kernel(int M, int N, int K,
                  const float* __restrict__ A, int lda,
                  const float* __restrict__ B, int ldb,
                  float* __restrict__ C, int ldc)
{
    __shared__ float As[8][128];
    __shared__ float Bs[8][128];
    int tid = threadIdx.x;
    int m0 = blockIdx.y * 128;
    int n0 = blockIdx.x * 128;
    int tx = tid % 16, ty = tid / 16;
    float acc[8][8];
    #pragma unroll
    for (int i = 0; i < 8; i++)
        #pragma unroll
        for (int j = 0; j < 8; j++) acc[i][j] = 0.f;

    int arow = tid / 2;
    int acol = (tid % 2) * 4;
    int brow = tid / 32;
    int bcol = (tid % 32) * 4;

    for (int kt = 0; kt < K; kt += 8) {
        #pragma unroll
        for (int j = 0; j < 4; j++) {
            int m = m0 + arow, k = kt + acol + j;
            As[acol + j][arow] = (m < M && k < K) ? A[(long long)m*lda + k] : 0.f;
        }
        #pragma unroll
        for (int j = 0; j < 4; j++) {
            int k = kt + brow, n = n0 + bcol + j;
            Bs[brow][bcol + j] = (k < K && n < N) ? B[(long long)k*ldb + n] : 0.f;
        }
        __syncthreads();
        #pragma unroll
        for (int kk = 0; kk < 8; kk++) {
            float a[8], b[8];
            #pragma unroll
            for (int i = 0; i < 4; i++) { a[i] = As[kk][ty*4+i]; a[4+i] = As[kk][64+ty*4+i]; }
            #pragma unroll
            for (int j = 0; j < 4; j++) { b[j] = Bs[kk][tx*4+j]; b[4+j] = Bs[kk][64+tx*4+j]; }
            #pragma unroll
            for (int i = 0; i < 8; i++)
                #pragma unroll
                for (int j = 0; j < 8; j++) acc[i][j] += a[i] * b[j];
        }
        __syncthreads();
    }
    #pragma unroll
    for (int i = 0; i < 8; i++) {
        int m = m0 + (i < 4 ? ty*4+i : 64 + ty*4 + (i-4));
        if (m >= M) continue;
        #pragma unroll
        for (int j = 0; j < 8; j++) {
            int n = n0 + (j < 4 ? tx*4+j : 64 + tx*4 + (j-4));
            if (n < N) C[(long long)m*ldc + n] = acc[i][j];
        }
    }
}

// --------------- tensor-core support GEMM: C = S @ B (split bf16) -----------
__global__ __launch_bounds__(256)
void tgemm_kernel(int M, int N,
                  const __nv_bfloat16* __restrict__ Ah,
                  const __nv_bfloat16* __restrict__ Al,
                  const float* __restrict__ B, int ldb,
                  float* __restrict__ C, int ldc)
{
    __shared__ __nv_bfloat16 sAh[128][40];
    __shared__ __nv_bfloat16 sAl[128][40];
    __shared__ __nv_bfloat16 sBh[32][136];
    __shared__ __nv_bfloat16 sBl[32][136];

    int tid  = threadIdx.x;
    int warp = tid >> 5, lane = tid & 31;
    int m0 = blockIdx.y * 128, n0 = blockIdx.x * 128;
    int wm = (warp >> 2) * 64, wn = (warp & 3) * 32;

    float acc[4][4][4];
    #pragma unroll
    for (int i = 0; i < 4; i++)
        #pragma unroll
        for (int j = 0; j < 4; j++)
            #pragma unroll
            for (int q = 0; q < 4; q++) acc[i][j][q] = 0.f;

    int ar = tid >> 1, ac = (tid & 1) * 16;
    int bk = tid >> 3, bn = (tid & 7) * 16;

    for (int kt = 0; kt < KTPAD/32; kt++) {
        {
            bool mok = (m0 + ar) < M;
            const __nv_bfloat16* gh = Ah + (long long)(m0 + ar)*KTPAD + kt*32 + ac;
            const __nv_bfloat16* gl = Al + (long long)(m0 + ar)*KTPAD + kt*32 + ac;
            #pragma unroll
            for (int j = 0; j < 16; j += 2) {
                unsigned vh = mok ? *(const unsigned*)(gh + j) : 0u;
                unsigned vl = mok ? *(const unsigned*)(gl + j) : 0u;
                *(unsigned*)&sAh[ar][ac + j] = vh;
                *(unsigned*)&sAl[ar][ac + j] = vl;
            }
        }
        {
            int kg = kt*32 + bk;
            if (kg < NNODE) {
                const float* gb = B + (long long)kg*ldb + n0 + bn;
                #pragma unroll
                for (int j = 0; j < 16; j += 4) {
                    float4 v = *(const float4*)(gb + j);
                    split2(v.x, v.y, (__nv_bfloat162*)&sBh[bk][bn + j],     (__nv_bfloat162*)&sBl[bk][bn + j]);
                    split2(v.z, v.w, (__nv_bfloat162*)&sBh[bk][bn + j + 2], (__nv_bfloat162*)&sBl[bk][bn + j + 2]);
                }
            } else {
                #pragma unroll
                for (int j = 0; j < 16; j += 2) {
                    *(unsigned*)&sBh[bk][bn + j] = 0u;
                    *(unsigned*)&sBl[bk][bn + j] = 0u;
                }
            }
        }
        __syncthreads();

        #pragma unroll
        for (int ks = 0; ks < 2; ks++) {
            unsigned afh[4][4], afl[4][4], bfh[4][2], bfl[4][2];
            #pragma unroll
            for (int mi = 0; mi < 4; mi++) {
                int row = wm + mi*16 + (lane & 15);
                int col = ks*16 + (lane >> 4) * 8;
                ldsm_x4(afh[mi], (unsigned)__cvta_generic_to_shared(&sAh[row][col]));
                ldsm_x4(afl[mi], (unsigned)__cvta_generic_to_shared(&sAl[row][col]));
            }
            #pragma unroll
            for (int np = 0; np < 2; np++) {
                int k  = ks*16 + (lane & 15);
                int nn = wn + np*16 + (lane >> 4) * 8;
                unsigned r[4];
                ldsm_x4t(r, (unsigned)__cvta_generic_to_shared(&sBh[k][nn]));
                bfh[np*2][0] = r[0]; bfh[np*2][1] = r[1];
                bfh[np*2+1][0] = r[2]; bfh[np*2+1][1] = r[3];
                ldsm_x4t(r, (unsigned)__cvta_generic_to_shared(&sBl[k][nn]));
                bfl[np*2][0] = r[0]; bfl[np*2][1] = r[1];
                bfl[np*2+1][0] = r[2]; bfl[np*2+1][1] = r[3];
            }
            #pragma unroll
            for (int mi = 0; mi < 4; mi++)
                #pragma unroll
                for (int ni = 0; ni < 4; ni++) {
                    mma16816(acc[mi][ni], afh[mi], bfh[ni]);
                    mma16816(acc[mi][ni], afh[mi], bfl[ni]);
                    mma16816(acc[mi][ni], afl[mi], bfh[ni]);
                }
        }
        __syncthreads();
    }

    int g = lane >> 2, tq = lane & 3;
    #pragma unroll
    for (int mi = 0; mi < 4; mi++) {
        #pragma unroll
        for (int ni = 0; ni < 4; ni++) {
            int row = m0 + wm + mi*16 + g;
            int col = n0 + wn + ni*8 + tq*2;
            if (row < M)
                *(float2*)&C[(long long)row*ldc + col] = make_float2(acc[mi][ni][0], acc[mi][ni][1]);
            if (row + 8 < M)
                *(float2*)&C[(long long)(row+8)*ldc + col] = make_float2(acc[mi][ni][2], acc[mi][ni][3]);
        }
    }
}

// ---------------------- per-node weight projection (bf16 hi/lo) -------------
__global__ void project_Wg_kernel(const float* __restrict__ E, const float* __restrict__ Wg,
                                  __nv_bfloat16* __restrict__ Wh, __nv_bfloat16* __restrict__ Wl, int l) {
    int kc = blockIdx.x, n = blockIdx.y, o = threadIdx.x;
    const float* er = E + n*DE;
    float acc = 0.f;
    #pragma unroll
    for (int d = 0; d < DE; d++) acc += er[d] * Wg[((l*DE + d)*GK + kc)*128 + o];
    __nv_bfloat16 h = __float2bfloat16(acc);
    long long idx = ((long long)n*GK + kc)*128 + o;
    Wh[idx] = h;
    Wl[idx] = __float2bfloat16(acc - __bfloat162float(h));
}
__global__ void project_Wc_kernel(const float* __restrict__ E, const float* __restrict__ Wc,
                                  __nv_bfloat16* __restrict__ Wh, __nv_bfloat16* __restrict__ Wl, int l) {
    int kc = blockIdx.x, n = blockIdx.y, o = threadIdx.x;
    const float* er = E + n*DE;
    float acc = 0.f;
    #pragma unroll
    for (int d = 0; d < DE; d++) acc += er[d] * Wc[((l*DE + d)*CK + kc)*64 + o];
    __nv_bfloat16 h = __float2bfloat16(acc);
    long long idx = ((long long)n*CK + kc)*64 + o;
    Wh[idx] = h;
    Wl[idx] = __float2bfloat16(acc - __bfloat162float(h));
}
__global__ void project_bg_kernel(const float* __restrict__ E, const float* __restrict__ bg,
                                  float* __restrict__ bgn, int l) {
    int n = blockIdx.x, o = threadIdx.x;
    float acc = 0.f;
    #pragma unroll
    for (int d = 0; d < DE; d++) acc += E[n*DE+d] * bg[(l*DE + d)*128 + o];
    bgn[n*128 + o] = acc;
}
__global__ void project_bc_kernel(const float* __restrict__ E, const float* __restrict__ bc,
                                  float* __restrict__ bcn, int l) {
    int n = blockIdx.x, o = threadIdx.x;
    float acc = 0.f;
    #pragma unroll
    for (int d = 0; d < DE; d++) acc += E[n*DE+d] * bc[(l*DE + d)*64 + o];
    bcn[n*64 + o] = acc;
}

// ----------------------------- data movement --------------------------------
__global__ void window_avg_l0_kernel(const float* __restrict__ x, float* __restrict__ XA) {
    long long idx = (long long)blockIdx.x*blockDim.x + threadIdx.x;
    if (idx >= TNBO) return;
    int c = (int)(idx % DOUT);
    int b = (int)((idx / DOUT) % BB);
    int n = (int)((idx / (DOUT*BB)) % NNODE);
    int t = (int)(idx / ((long long)DOUT*BB*NNODE));
    long long base = (((long long)b*TT + t)*NNODE + n)*DOUT + c;
    const long long dT = (long long)NNODE*DOUT;
    float v;
    if (t == 0 || t == TT-1) v = x[base];
    else v = (x[base - dT] + x[base] + x[base + dT]) * (1.f/3.f);
    XA[idx] = v;
}

__global__ void window_avg_kernel(const float* __restrict__ IN, float* __restrict__ XA) {
    int idx = blockIdx.x*blockDim.x + threadIdx.x;
    if (idx >= TNBO) return;
    int t = idx / NBO;
    if (t == 0 || t == TT-1) XA[idx] = IN[idx];
    else XA[idx] = (IN[idx-NBO] + IN[idx] + IN[idx+NBO]) * (1.f/3.f);
}

__global__ void init_state_kernel(const float* __restrict__ h0, const float* __restrict__ c0,
                                  float* __restrict__ XIN, int l) {
    int idx = blockIdx.x*blockDim.x + threadIdx.x;
    if (idx >= NBO) return;
    int o = idx % DOUT;
    int b = (idx / DOUT) % BB;
    int n = idx / (DOUT*BB);
    int src = ((l*BB + b)*NNODE + n)*DOUT + o;
    XIN[(n*BB + b)*CG + 64  + o] = h0[src];
    XIN[(n*BB + b)*CG + 128 + o] = c0[src];
}

__global__ void prep_step_kernel(const float* __restrict__ XA, float* __restrict__ XIN, int t) {
    int idx = blockIdx.x*blockDim.x + threadIdx.x;
    if (idx >= NBO) return;
    int o  = idx % DOUT;
    int nb = idx / DOUT;
    XIN[nb*CG + o] = XA[(long long)t*NBO + idx];
}

// -------- gate: per-node TC GEMM (64x128x960) + sigmoid + r*h ---------------
__global__ __launch_bounds__(256)
void gate_tc_kernel(const float* __restrict__ XG, const float* __restrict__ XIN,
                    const __nv_bfloat16* __restrict__ Wh, const __nv_bfloat16* __restrict__ Wl,
                    const float* __restrict__ bgn,
                    float* __restrict__ Z, float* __restrict__ RH)
{
    const int n = blockIdx.x;
    __shared__ __nv_bfloat16 sAh[64][40], sAl[64][40];
    __shared__ __nv_bfloat16 sBh[32][136], sBl[32][136];
    int tid = threadIdx.x, warp = tid >> 5, lane = tid & 31;
    int wm = (warp >> 1) * 16, wn = (warp & 1) * 64;

    float acc[8][4];
    #pragma unroll
    for (int i = 0; i < 8; i++)
        #pragma unroll
        for (int q = 0; q < 4; q++) acc[i][q] = 0.f;

    int ar = tid >> 2, ac8 = (tid & 3) * 8;     // A: 64 rows x 32 cols
    int br = tid >> 3, bc16 = (tid & 7) * 16;   // B: 32 rows x 128 cols
    const __nv_bfloat16* Wnh = Wh + (long long)n * GK * 128;
    const __nv_bfloat16* Wnl = Wl + (long long)n * GK * 128;

    for (int kt = 0; kt < GK/32; kt++) {
        int kk0 = kt * 32;
        int ksup = kk0 / CG, cb = kk0 % CG;
        {
            const float* Abase = (ksup == 0)
                ? XIN + (long long)(n*BB)*CG
                : XG  + (((long long)(ksup-1)*NNODE + n)*BB)*CG;
            const float* ga = Abase + ar*CG + cb + ac8;
            #pragma unroll
            for (int j = 0; j < 8; j += 4) {
                float4 v = *(const float4*)(ga + j);
                split2(v.x, v.y, (__nv_bfloat162*)&sAh[ar][ac8 + j],     (__nv_bfloat162*)&sAl[ar][ac8 + j]);
                split2(v.z, v.w, (__nv_bfloat162*)&sAh[ar][ac8 + j + 2], (__nv_bfloat162*)&sAl[ar][ac8 + j + 2]);
            }
        }
        {
            const __nv_bfloat16* gh = Wnh + (long long)(kk0 + br)*128 + bc16;
            const __nv_bfloat16* gl = Wnl + (long long)(kk0 + br)*128 + bc16;
            *(uint4*)&sBh[br][bc16]     = *(const uint4*)gh;
            *(uint4*)&sBh[br][bc16 + 8] = *(const uint4*)(gh + 8);
            *(uint4*)&sBl[br][bc16]     = *(const uint4*)gl;
            *(uint4*)&sBl[br][bc16 + 8] = *(const uint4*)(gl + 8);
        }
        __syncthreads();

        #pragma unroll
        for (int ks = 0; ks < 2; ks++) {
            unsigned ah[4], al[4];
            {
                int row = wm + (lane & 15);
                int col = ks*16 + (lane >> 4) * 8;
                ldsm_x4(ah, (unsigned)__cvta_generic_to_shared(&sAh[row][col]));
                ldsm_x4(al, (unsigned)__cvta_generic_to_shared(&sAl[row][col]));
            }
            unsigned bh[8][2], bl[8][2];
            #pragma unroll
            for (int np = 0; np < 4; np++) {
                int k  = ks*16 + (lane & 15);
                int nn = wn + np*16 + (lane >> 4) * 8;
                unsigned r[4];
                ldsm_x4t(r, (unsigned)__cvta_generic_to_shared(&sBh[k][nn]));
                bh[np*2][0] = r[0]; bh[np*2][1] = r[1];
                bh[np*2+1][0] = r[2]; bh[np*2+1][1] = r[3];
                ldsm_x4t(r, (unsigned)__cvta_generic_to_shared(&sBl[k][nn]));
                bl[np*2][0] = r[0]; bl[np*2][1] = r[1];
                bl[np*2+1][0] = r[2]; bl[np*2+1][1] = r[3];
            }
            #pragma unroll
            for (int ni = 0; ni < 8; ni++) {
                mma16816(acc[ni], ah, bh[ni]);
                mma16816(acc[ni], ah, bl[ni]);
                mma16816(acc[ni], al, bh[ni]);
            }
        }
        __syncthreads();
    }

    const float* brow = bgn + n*128;
    int g = lane >> 2, q = lane & 3;
    #pragma unroll
    for (int ni = 0; ni < 8; ni++) {
        #pragma unroll
        for (int d = 0; d < 4; d++) {
            int row = wm + g + ((d >= 2) ? 8 : 0);
            int col = wn + ni*8 + q*2 + (d & 1);
            float v = acc[ni][d] + brow[col];
            float s = 1.f / (1.f + expf(-v));
            if (col < 64) {
                Z[(n*BB + row)*DOUT + col] = s;
            } else {
                int oo = col - 64;
                float h = XIN[(long long)(n*BB + row)*CG + 64 + oo];
                RH[(n*BB + row)*DOUT + oo] = s * h;
            }
        }
    }
}

// ------- candidate: per-node TC GEMM (64x64x640) + tanh + GRU/HiPPO ---------
__global__ __launch_bounds__(256)
void cand_tc_kernel(const float* __restrict__ XG, const float* __restrict__ XIN,
                    const float* __restrict__ RH, const float* __restrict__ XGR,
                    const __nv_bfloat16* __restrict__ Wh, const __nv_bfloat16* __restrict__ Wl,
                    const float* __restrict__ bcn, const float* __restrict__ Z,
                    float* __restrict__ XINout, float* __restrict__ OUT,
                    int t, int is_final, float ca, float cb)
{
    const int n = blockIdx.x;
    __shared__ __nv_bfloat16 sAh[64][40], sAl[64][40];
    __shared__ __nv_bfloat16 sBh[32][72], sBl[32][72];
    int tid = threadIdx.x, warp = tid >> 5, lane = tid & 31;
    int wm = (warp >> 1) * 16, wn = (warp & 1) * 32;

    float acc[4][4];
    #pragma unroll
    for (int i = 0; i < 4; i++)
        #pragma unroll
        for (int q = 0; q < 4; q++) acc[i][q] = 0.f;

    int ar = tid >> 2, ac8 = (tid & 3) * 8;     // A: 64x32
    int br = tid >> 3, bc8 = (tid & 7) * 8;     // B: 32x64
    const __nv_bfloat16* Wnh = Wh + (long long)n * CK * 64;
    const __nv_bfloat16* Wnl = Wl + (long long)n * CK * 64;

    for (int kt = 0; kt < CK/32; kt++) {
        int kk0 = kt * 32;
        int ksup = kk0 / CC, cw = kk0 % CC;
        {
            const float* Abase;
            int astride;
            if (cw < 64) {
                astride = CG;
                Abase = (ksup == 0)
                    ? XIN + (long long)(n*BB)*CG + cw
                    : XG  + (((long long)(ksup-1)*NNODE + n)*BB)*CG + cw;
            } else {
                astride = DOUT;
                Abase = (ksup == 0)
                    ? RH  + (long long)(n*BB)*DOUT + (cw - 64)
                    : XGR + (((long long)(ksup-1)*NNODE + n)*BB)*DOUT + (cw - 64);
            }
            const float* ga = Abase + ar*astride + ac8;
            #pragma unroll
            for (int j = 0; j < 8; j += 4) {
                float4 v = *(const float4*)(ga + j);
                split2(v.x, v.y, (__nv_bfloat162*)&sAh[ar][ac8 + j],     (__nv_bfloat162*)&sAl[ar][ac8 + j]);
                split2(v.z, v.w, (__nv_bfloat162*)&sAh[ar][ac8 + j + 2], (__nv_bfloat162*)&sAl[ar][ac8 + j + 2]);
            }
        }
        {
            const __nv_bfloat16* gh = Wnh + (long long)(kk0 + br)*64 + bc8;
            const __nv_bfloat16* gl = Wnl + (long long)(kk0 + br)*64 + bc8;
            *(uint4*)&sBh[br][bc8] = *(const uint4*)gh;
            *(uint4*)&sBl[br][bc8] = *(const uint4*)gl;
        }
        __syncthreads();

        #pragma unroll
        for (int ks = 0; ks < 2; ks++) {
            unsigned ah[4], al[4];
            {
                int row = wm + (lane & 15);
                int col = ks*16 + (lane >> 4) * 8;
                ldsm_x4(ah, (unsigned)__cvta_generic_to_shared(&sAh[row][col]));
                ldsm_x4(al, (unsigned)__cvta_generic_to_shared(&sAl[row][col]));
            }
            unsigned bh[4][2], bl[4][2];
            #pragma unroll
            for (int np = 0; np < 2; np++) {
                int k  = ks*16 + (lane & 15);
                int nn = wn + np*16 + (lane >> 4) * 8;
                unsigned r[4];
                ldsm_x4t(r, (unsigned)__cvta_generic_to_shared(&sBh[k][nn]));
                bh[np*2][0] = r[0]; bh[np*2][1] = r[1];
                bh[np*2+1][0] = r[2]; bh[np*2+1][1] = r[3];
                ldsm_x4t(r, (unsigned)__cvta_generic_to_shared(&sBl[k][nn]));
                bl[np*2][0] = r[0]; bl[np*2][1] = r[1];
                bl[np*2+1][0] = r[2]; bl[np*2+1][1] = r[3];
            }
            #pragma unroll
            for (int ni = 0; ni < 4; ni++) {
                mma16816(acc[ni], ah, bh[ni]);
                mma16816(acc[ni], ah, bl[ni]);
                mma16816(acc[ni], al, bh[ni]);
            }
        }
        __syncthreads();
    }

    const float* brow = bcn + n*64;
    int g = lane >> 2, q = lane & 3;
    #pragma unroll
    for (int ni = 0; ni < 4; ni++) {
        #pragma unroll
        for (int d = 0; d < 4; d++) {
            int row = wm + g + ((d >= 2) ? 8 : 0);   // batch b
            int col = wn + ni*8 + q*2 + (d & 1);     // output o
            float hc = tanhf(acc[ni][d] + brow[col]);
            float z  = Z[(n*BB + row)*DOUT + col];
            long long ih = (long long)(n*BB + row)*CG + 64 + col;
            float h_old = XINout[ih];
            float c_old = XINout[ih + 64];
            float h_new = z*h_old + (1.f - z)*hc;
            float c_new = ca*c_old + cb*h_new;
            XINout[ih]      = h_new;
            XINout[ih + 64] = c_new;
            if (is_final) OUT[(((long long)row*TT + t)*NNODE + n)*DOUT + col] = h_new;
            else          OUT[(((long long)t*NNODE + n)*BB + row)*DOUT + col] = h_new;
        }
    }
}

// -------------------------------- driver ------------------------------------
extern "C" void kernel_launch(void* const* d_in, const int* in_sizes, int n_in,
                              void* d_out, int out_size)
{
    const float* x   = (const float*)d_in[0];
    const float* h0  = (const float*)d_in[1];
    const float* c0  = (const float*)d_in[2];
    const float* E   = (const float*)d_in[3];
    const float* adj = (const float*)d_in[4];
    const float* Wg  = (const float*)d_in[5];
    const float* bg  = (const float*)d_in[6];
    const float* Wc  = (const float*)d_in[7];
    const float* bc  = (const float*)d_in[8];
    float* out = (float*)d_out;
    (void)in_sizes; (void)n_in; (void)out_size;

    float *SS, *bgn, *bcn, *XA, *HS, *XIN, *RH, *XG, *XGR, *Z;
    __nv_bfloat16 *Shi, *Slo, *Wgh, *Wgl, *Wch, *Wcl;
    cudaGetSymbolAddress((void**)&SS,  g_SS);
    cudaGetSymbolAddress((void**)&Shi, g_Shi);
    cudaGetSymbolAddress((void**)&Slo, g_Slo);
    cudaGetSymbolAddress((void**)&Wgh, g_Wgh);
    cudaGetSymbolAddress((void**)&Wgl, g_Wgl);
    cudaGetSymbolAddress((void**)&bgn, g_bgn);
    cudaGetSymbolAddress((void**)&Wch, g_Wch);
    cudaGetSymbolAddress((void**)&Wcl, g_Wcl);
    cudaGetSymbolAddress((void**)&bcn, g_bcn);
    cudaGetSymbolAddress((void**)&XA,  g_XA);
    cudaGetSymbolAddress((void**)&HS,  g_HS);
    cudaGetSymbolAddress((void**)&XIN, g_XIN);
    cudaGetSymbolAddress((void**)&RH,  g_RH);
    cudaGetSymbolAddress((void**)&XG,  g_XG);
    cudaGetSymbolAddress((void**)&XGR, g_XGR);
    cudaGetSymbolAddress((void**)&Z,   g_Z);

    // ---- supports ----
    build_A_kernel   <<<NNODE, 256>>>(E,   SS + 0*NN);
    build_adjn_kernel<<<NNODE, 256>>>(adj, SS + 2*NN);
    dim3 g307((NNODE+127)/128, (NNODE+127)/128);
    sgemm_kernel<<<g307, 256>>>(NNODE, NNODE, NNODE, SS+0*NN, NNODE, SS+0*NN, NNODE, SS+1*NN, NNODE);
    cheb_fix_kernel<<<(NN+255)/256, 256>>>(SS + 1*NN);
    sgemm_kernel<<<g307, 256>>>(NNODE, NNODE, NNODE, SS+2*NN, NNODE, SS+2*NN, NNODE, SS+3*NN, NNODE);
    split_S_kernel<<<(MG*KTPAD + 255)/256, 256>>>(SS, Shi, Slo);

    for (int l = 0; l < 2; l++) {
        if (l == 0) window_avg_l0_kernel<<<(TNBO+255)/256, 256>>>(x, XA);
        else        window_avg_kernel   <<<(TNBO+255)/256, 256>>>(HS, XA);
        project_Wg_kernel<<<dim3(GK, NNODE), 128>>>(E, Wg, Wgh, Wgl, l);
        project_bg_kernel<<<NNODE, 128>>>(E, bg, bgn, l);
        project_Wc_kernel<<<dim3(CK, NNODE), 64>>>(E, Wc, Wch, Wcl, l);
        project_bc_kernel<<<NNODE, 64>>>(E, bc, bcn, l);
        init_state_kernel<<<(NBO+255)/256, 256>>>(h0, c0, XIN, l);

        for (int t = 0; t < TT; t++) {
            prep_step_kernel<<<(NBO+255)/256, 256>>>(XA, XIN, t);

            // XG = S @ XIN  (1228 x 12288 x 307)
            dim3 g1((BB*CG)/128, (MG+127)/128);
            tgemm_kernel<<<g1, 256>>>(MG, BB*CG, Shi, Slo, XIN, BB*CG, XG, BB*CG);

            gate_tc_kernel<<<NNODE, 256>>>(XG, XIN, Wgh, Wgl, bgn, Z, RH);

            // XGR = S @ RH  (1228 x 4096 x 307)
            dim3 g3((BB*DOUT)/128, (MG+127)/128);
            tgemm_kernel<<<g3, 256>>>(MG, BB*DOUT, Shi, Slo, RH, BB*DOUT, XGR, BB*DOUT);

            float ca = (float)t / (float)(t + 1);
            float cb = 1.f / (float)(t + 1);
            cand_tc_kernel<<<NNODE, 256>>>(XG, XIN, RH, XGR, Wch, Wcl, bcn, Z, XIN,
                                           (l == 1) ? out : HS, t, (l == 1), ca, cb);
        }
    }
}

// round 10
// speedup vs baseline: 2.3664x; 1.3039x over previous
#include <cuda_runtime.h>
#include <cuda_bf16.h>
#include <math.h>

// ---------------------------------------------------------------------------
// AVWDCRNN: adaptive-graph-conv GRU with HiPPO c-state.
// B=64, T=12, N=307, Din=Dout=64, L=2, De=16, K=5 supports.
// Round 10: retry of the Round-9 register-prefetch pipeline (content is
// ingredient-identical to the passing R7: static smem <=48KB, only
// ldmatrix/mma.sync/plain loads, ~430MB scratch). Mainloops:
//   sync; store regs(kt)->smem; sync; load(kt+1)->regs; mma(kt).
// ---------------------------------------------------------------------------

#define NNODE 307
#define BB    64
#define TT    12
#define DOUT  64
#define DE    16
#define KSUP  5
#define KR    4
#define CG    192
#define CC    128
#define GK    (KSUP*CG)      // 960
#define CK    (KSUP*CC)      // 640
#define NN    (NNODE*NNODE)
#define NB    (NNODE*BB)
#define NBO   (NB*DOUT)
#define TNBO  (TT*NBO)
#define MG    (KR*NNODE)     // 1228
#define KTPAD 320

// ------------------------------- scratch -----------------------------------
__device__ float g_SS [KR*NN];
__device__ __nv_bfloat16 g_Shi[MG*KTPAD];
__device__ __nv_bfloat16 g_Slo[MG*KTPAD];
__device__ __nv_bfloat16 g_Wgh[NNODE*GK*128];
__device__ __nv_bfloat16 g_Wgl[NNODE*GK*128];
__device__ float g_bgn[NNODE*128];
__device__ __nv_bfloat16 g_Wch[NNODE*CK*64];
__device__ __nv_bfloat16 g_Wcl[NNODE*CK*64];
__device__ float g_bcn[NNODE*64];
__device__ float g_XA [TNBO];
__device__ float g_HS [TNBO];
__device__ float g_XIN[NB*CG];
__device__ float g_RH [NB*DOUT];
__device__ float g_XG [KR*NB*CG];
__device__ float g_XGR[KR*NB*DOUT];
__device__ float g_Z  [NB*DOUT];

// --------------------------- asm helpers ------------------------------------
__device__ __forceinline__ void ldsm_x4(unsigned* r, unsigned addr) {
    asm volatile("ldmatrix.sync.aligned.m8n8.x4.shared.b16 {%0,%1,%2,%3}, [%4];"
                 : "=r"(r[0]), "=r"(r[1]), "=r"(r[2]), "=r"(r[3]) : "r"(addr));
}
__device__ __forceinline__ void ldsm_x4t(unsigned* r, unsigned addr) {
    asm volatile("ldmatrix.sync.aligned.m8n8.x4.trans.shared.b16 {%0,%1,%2,%3}, [%4];"
                 : "=r"(r[0]), "=r"(r[1]), "=r"(r[2]), "=r"(r[3]) : "r"(addr));
}
__device__ __forceinline__ void mma16816(float* d, const unsigned* a, const unsigned* b) {
    asm volatile("mma.sync.aligned.m16n8k16.row.col.f32.bf16.bf16.f32 "
                 "{%0,%1,%2,%3},{%4,%5,%6,%7},{%8,%9},{%0,%1,%2,%3};"
                 : "+f"(d[0]), "+f"(d[1]), "+f"(d[2]), "+f"(d[3])
                 : "r"(a[0]), "r"(a[1]), "r"(a[2]), "r"(a[3]), "r"(b[0]), "r"(b[1]));
}
__device__ __forceinline__ void split2(float x, float y, __nv_bfloat162* hi, __nv_bfloat162* lo) {
    __nv_bfloat16 h0 = __float2bfloat16(x), h1 = __float2bfloat16(y);
    *hi = __halves2bfloat162(h0, h1);
    *lo = __halves2bfloat162(__float2bfloat16(x - __bfloat162float(h0)),
                             __float2bfloat16(y - __bfloat162float(h1)));
}

// ------------------------- supports construction ----------------------------
__global__ void build_A_kernel(const float* __restrict__ E, float* __restrict__ A) {
    __shared__ float row[NNODE];
    __shared__ float er[DE];
    __shared__ float red[256];
    int i = blockIdx.x, tid = threadIdx.x;
    if (tid < DE) er[tid] = E[i*DE + tid];
    __syncthreads();
    for (int j = tid; j < NNODE; j += 256) {
        float s = 0.f;
        #pragma unroll
        for (int d = 0; d < DE; d++) s += er[d] * E[j*DE + d];
        row[j] = fmaxf(s, 0.f);
    }
    __syncthreads();
    float m = -1e30f;
    for (int j = tid; j < NNODE; j += 256) m = fmaxf(m, row[j]);
    red[tid] = m; __syncthreads();
    for (int s = 128; s > 0; s >>= 1) { if (tid < s) red[tid] = fmaxf(red[tid], red[tid+s]); __syncthreads(); }
    m = red[0]; __syncthreads();
    float sum = 0.f;
    for (int j = tid; j < NNODE; j += 256) { float e = expf(row[j]-m); row[j] = e; sum += e; }
    red[tid] = sum; __syncthreads();
    for (int s = 128; s > 0; s >>= 1) { if (tid < s) red[tid] += red[tid+s]; __syncthreads(); }
    float inv = 1.f / red[0];
    for (int j = tid; j < NNODE; j += 256) A[i*NNODE + j] = row[j] * inv;
}

__global__ void build_adjn_kernel(const float* __restrict__ adj, float* __restrict__ out) {
    __shared__ float red[256];
    int i = blockIdx.x, tid = threadIdx.x;
    float sum = 0.f;
    for (int j = tid; j < NNODE; j += 256) sum += adj[i*NNODE + j];
    red[tid] = sum; __syncthreads();
    for (int s = 128; s > 0; s >>= 1) { if (tid < s) red[tid] += red[tid+s]; __syncthreads(); }
    float inv = 1.f / (red[0] + 1e-8f);
    for (int j = tid; j < NNODE; j += 256) out[i*NNODE + j] = adj[i*NNODE + j] * inv;
}

__global__ void cheb_fix_kernel(float* __restrict__ S1) {
    int idx = blockIdx.x*blockDim.x + threadIdx.x;
    if (idx >= NN) return;
    float v = 2.f * S1[idx];
    if (idx / NNODE == idx % NNODE) v -= 1.f;
    S1[idx] = v;
}

__global__ void split_S_kernel(const float* __restrict__ SS,
                               __nv_bfloat16* __restrict__ Shi,
                               __nv_bfloat16* __restrict__ Slo) {
    int idx = blockIdx.x*blockDim.x + threadIdx.x;
    if (idx >= MG*KTPAD) return;
    int m = idx / KTPAD, k = idx % KTPAD;
    float v = (k < NNODE) ? SS[m*NNODE + k] : 0.f;
    __nv_bfloat16 h = __float2bfloat16(v);
    Shi[idx] = h;
    Slo[idx] = __float2bfloat16(v - __bfloat162float(h));
}

// ------------------------- generic SGEMM (row-major) ------------------------
__global__ __launch_bounds__(256)
void sgemm_kernel(int M, int N, int K,
                  const float* __restrict__ A, int lda,
                  const float* __restrict__ B, int ldb,
                  float* __restrict__ C, int ldc)
{
    __shared__ float As[8][128];
    __shared__ float Bs[8][128];
    int tid = threadIdx.x;
    int m0 = blockIdx.y * 128;
    int n0 = blockIdx.x * 128;
    int tx = tid % 16, ty = tid / 16;
    float acc[8][8];
    #pragma unroll
    for (int i = 0; i < 8; i++)
        #pragma unroll
        for (int j = 0; j < 8; j++) acc[i][j] = 0.f;

    int arow = tid / 2;
    int acol = (tid % 2) * 4;
    int brow = tid / 32;
    int bcol = (tid % 32) * 4;

    for (int kt = 0; kt < K; kt += 8) {
        #pragma unroll
        for (int j = 0; j < 4; j++) {
            int m = m0 + arow, k = kt + acol + j;
            As[acol + j][arow] = (m < M && k < K) ? A[(long long)m*lda + k] : 0.f;
        }
        #pragma unroll
        for (int j = 0; j < 4; j++) {
            int k = kt + brow, n = n0 + bcol + j;
            Bs[brow][bcol + j] = (k < K && n < N) ? B[(long long)k*ldb + n] : 0.f;
        }
        __syncthreads();
        #pragma unroll
        for (int kk = 0; kk < 8; kk++) {
            float a[8], b[8];
            #pragma unroll
            for (int i = 0; i < 4; i++) { a[i] = As[kk][ty*4+i]; a[4+i] = As[kk][64+ty*4+i]; }
            #pragma unroll
            for (int j = 0; j < 4; j++) { b[j] = Bs[kk][tx*4+j]; b[4+j] = Bs[kk][64+tx*4+j]; }
            #pragma unroll
            for (int i = 0; i < 8; i++)
                #pragma unroll
                for (int j = 0; j < 8; j++) acc[i][j] += a[i] * b[j];
        }
        __syncthreads();
    }
    #pragma unroll
    for (int i = 0; i < 8; i++) {
        int m = m0 + (i < 4 ? ty*4+i : 64 + ty*4 + (i-4));
        if (m >= M) continue;
        #pragma unroll
        for (int j = 0; j < 8; j++) {
            int n = n0 + (j < 4 ? tx*4+j : 64 + tx*4 + (j-4));
            if (n < N) C[(long long)m*ldc + n] = acc[i][j];
        }
    }
}

// --------------- tensor-core support GEMM: C = S @ B (reg-prefetch) ---------
__global__ __launch_bounds__(256)
void tgemm_kernel(int M, int N,
                  const __nv_bfloat16* __restrict__ Ah,
                  const __nv_bfloat16* __restrict__ Al,
                  const float* __restrict__ B, int ldb,
                  float* __restrict__ C, int ldc)
{
    __shared__ __nv_bfloat16 sAh[128][40];
    __shared__ __nv_bfloat16 sAl[128][40];
    __shared__ __nv_bfloat16 sBh[32][136];
    __shared__ __nv_bfloat16 sBl[32][136];

    int tid  = threadIdx.x;
    int warp = tid >> 5, lane = tid & 31;
    int m0 = blockIdx.y * 128, n0 = blockIdx.x * 128;
    int wm = (warp >> 2) * 64, wn = (warp & 3) * 32;

    float acc[4][4][4];
    #pragma unroll
    for (int i = 0; i < 4; i++)
        #pragma unroll
        for (int j = 0; j < 4; j++)
            #pragma unroll
            for (int q = 0; q < 4; q++) acc[i][j][q] = 0.f;

    int ar = tid >> 1, ac = (tid & 1) * 16;     // A: 128 rows x 32 halves
    int bk = tid >> 3, bn = (tid & 7) * 16;     // B: 32 rows x 128 floats

    int srow = m0 + ar; if (srow > M-1) srow = M-1;
    const __nv_bfloat16* gAh = Ah + (long long)srow*KTPAD + ac;
    const __nv_bfloat16* gAl = Al + (long long)srow*KTPAD + ac;

    uint4 rah0, rah1, ral0, ral1;
    float4 rb0, rb1, rb2, rb3;

#define TG_LOAD(kt_) {                                                            \
    rah0 = *(const uint4*)(gAh + (kt_)*32); rah1 = *(const uint4*)(gAh + (kt_)*32 + 8); \
    ral0 = *(const uint4*)(gAl + (kt_)*32); ral1 = *(const uint4*)(gAl + (kt_)*32 + 8); \
    int kg = (kt_)*32 + bk;                                                       \
    if (kg < NNODE) { const float* gb = B + (long long)kg*ldb + n0 + bn;          \
        rb0 = *(const float4*)gb;       rb1 = *(const float4*)(gb + 4);           \
        rb2 = *(const float4*)(gb + 8); rb3 = *(const float4*)(gb + 12); }        \
    else { rb0 = rb1 = rb2 = rb3 = make_float4(0.f,0.f,0.f,0.f); } }

#define TG_STORE() {                                                              \
    *(uint4*)&sAh[ar][ac] = rah0; *(uint4*)&sAh[ar][ac + 8] = rah1;               \
    *(uint4*)&sAl[ar][ac] = ral0; *(uint4*)&sAl[ar][ac + 8] = ral1;               \
    __nv_bfloat16* dh = &sBh[bk][bn]; __nv_bfloat16* dl = &sBl[bk][bn];           \
    split2(rb0.x, rb0.y, (__nv_bfloat162*)dh,      (__nv_bfloat162*)dl);          \
    split2(rb0.z, rb0.w, (__nv_bfloat162*)(dh+2),  (__nv_bfloat162*)(dl+2));      \
    split2(rb1.x, rb1.y, (__nv_bfloat162*)(dh+4),  (__nv_bfloat162*)(dl+4));      \
    split2(rb1.z, rb1.w, (__nv_bfloat162*)(dh+6),  (__nv_bfloat162*)(dl+6));      \
    split2(rb2.x, rb2.y, (__nv_bfloat162*)(dh+8),  (__nv_bfloat162*)(dl+8));      \
    split2(rb2.z, rb2.w, (__nv_bfloat162*)(dh+10), (__nv_bfloat162*)(dl+10));     \
    split2(rb3.x, rb3.y, (__nv_bfloat162*)(dh+12), (__nv_bfloat162*)(dl+12));     \
    split2(rb3.z, rb3.w, (__nv_bfloat162*)(dh+14), (__nv_bfloat162*)(dl+14)); }

    const int NT = KTPAD/32;   // 10
    TG_LOAD(0);
    for (int kt = 0; kt < NT; kt++) {
        __syncthreads();          // previous mma done before overwriting smem
        TG_STORE();
        __syncthreads();
        if (kt + 1 < NT) TG_LOAD(kt+1);   // latency overlaps mma below

        #pragma unroll
        for (int ks = 0; ks < 2; ks++) {
            unsigned afh[4][4], afl[4][4], bfh[4][2], bfl[4][2];
            #pragma unroll
            for (int mi = 0; mi < 4; mi++) {
                int row = wm + mi*16 + (lane & 15);
                int col = ks*16 + (lane >> 4) * 8;
                ldsm_x4(afh[mi], (unsigned)__cvta_generic_to_shared(&sAh[row][col]));
                ldsm_x4(afl[mi], (unsigned)__cvta_generic_to_shared(&sAl[row][col]));
            }
            #pragma unroll
            for (int np = 0; np < 2; np++) {
                int k  = ks*16 + (lane & 15);
                int nn = wn + np*16 + (lane >> 4) * 8;
                unsigned r[4];
                ldsm_x4t(r, (unsigned)__cvta_generic_to_shared(&sBh[k][nn]));
                bfh[np*2][0] = r[0]; bfh[np*2][1] = r[1];
                bfh[np*2+1][0] = r[2]; bfh[np*2+1][1] = r[3];
                ldsm_x4t(r, (unsigned)__cvta_generic_to_shared(&sBl[k][nn]));
                bfl[np*2][0] = r[0]; bfl[np*2][1] = r[1];
                bfl[np*2+1][0] = r[2]; bfl[np*2+1][1] = r[3];
            }
            #pragma unroll
            for (int mi = 0; mi < 4; mi++)
                #pragma unroll
                for (int ni = 0; ni < 4; ni++) {
                    mma16816(acc[mi][ni], afh[mi], bfh[ni]);
                    mma16816(acc[mi][ni], afh[mi], bfl[ni]);
                    mma16816(acc[mi][ni], afl[mi], bfh[ni]);
                }
        }
    }

    int g = lane >> 2, tq = lane & 3;
    #pragma unroll
    for (int mi = 0; mi < 4; mi++) {
        #pragma unroll
        for (int ni = 0; ni < 4; ni++) {
            int row = m0 + wm + mi*16 + g;
            int col = n0 + wn + ni*8 + tq*2;
            if (row < M)
                *(float2*)&C[(long long)row*ldc + col] = make_float2(acc[mi][ni][0], acc[mi][ni][1]);
            if (row + 8 < M)
                *(float2*)&C[(long long)(row+8)*ldc + col] = make_float2(acc[mi][ni][2], acc[mi][ni][3]);
        }
    }
#undef TG_LOAD
#undef TG_STORE
}

// ---------------------- per-node weight projection (bf16 hi/lo) -------------
__global__ void project_Wg_kernel(const float* __restrict__ E, const float* __restrict__ Wg,
                                  __nv_bfloat16* __restrict__ Wh, __nv_bfloat16* __restrict__ Wl, int l) {
    int kc = blockIdx.x, n = blockIdx.y, o = threadIdx.x;
    const float* er = E + n*DE;
    float acc = 0.f;
    #pragma unroll
    for (int d = 0; d < DE; d++) acc += er[d] * Wg[((l*DE + d)*GK + kc)*128 + o];
    __nv_bfloat16 h = __float2bfloat16(acc);
    long long idx = ((long long)n*GK + kc)*128 + o;
    Wh[idx] = h;
    Wl[idx] = __float2bfloat16(acc - __bfloat162float(h));
}
__global__ void project_Wc_kernel(const float* __restrict__ E, const float* __restrict__ Wc,
                                  __nv_bfloat16* __restrict__ Wh, __nv_bfloat16* __restrict__ Wl, int l) {
    int kc = blockIdx.x, n = blockIdx.y, o = threadIdx.x;
    const float* er = E + n*DE;
    float acc = 0.f;
    #pragma unroll
    for (int d = 0; d < DE; d++) acc += er[d] * Wc[((l*DE + d)*CK + kc)*64 + o];
    __nv_bfloat16 h = __float2bfloat16(acc);
    long long idx = ((long long)n*CK + kc)*64 + o;
    Wh[idx] = h;
    Wl[idx] = __float2bfloat16(acc - __bfloat162float(h));
}
__global__ void project_bg_kernel(const float* __restrict__ E, const float* __restrict__ bg,
                                  float* __restrict__ bgn, int l) {
    int n = blockIdx.x, o = threadIdx.x;
    float acc = 0.f;
    #pragma unroll
    for (int d = 0; d < DE; d++) acc += E[n*DE+d] * bg[(l*DE + d)*128 + o];
    bgn[n*128 + o] = acc;
}
__global__ void project_bc_kernel(const float* __restrict__ E, const float* __restrict__ bc,
                                  float* __restrict__ bcn, int l) {
    int n = blockIdx.x, o = threadIdx.x;
    float acc = 0.f;
    #pragma unroll
    for (int d = 0; d < DE; d++) acc += E[n*DE+d] * bc[(l*DE + d)*64 + o];
    bcn[n*64 + o] = acc;
}

// ----------------------------- data movement --------------------------------
__global__ void window_avg_l0_kernel(const float* __restrict__ x, float* __restrict__ XA) {
    long long idx = (long long)blockIdx.x*blockDim.x + threadIdx.x;
    if (idx >= TNBO) return;
    int c = (int)(idx % DOUT);
    int b = (int)((idx / DOUT) % BB);
    int n = (int)((idx / (DOUT*BB)) % NNODE);
    int t = (int)(idx / ((long long)DOUT*BB*NNODE));
    long long base = (((long long)b*TT + t)*NNODE + n)*DOUT + c;
    const long long dT = (long long)NNODE*DOUT;
    float v;
    if (t == 0 || t == TT-1) v = x[base];
    else v = (x[base - dT] + x[base] + x[base + dT]) * (1.f/3.f);
    XA[idx] = v;
}

__global__ void window_avg_kernel(const float* __restrict__ IN, float* __restrict__ XA) {
    int idx = blockIdx.x*blockDim.x + threadIdx.x;
    if (idx >= TNBO) return;
    int t = idx / NBO;
    if (t == 0 || t == TT-1) XA[idx] = IN[idx];
    else XA[idx] = (IN[idx-NBO] + IN[idx] + IN[idx+NBO]) * (1.f/3.f);
}

__global__ void init_state_kernel(const float* __restrict__ h0, const float* __restrict__ c0,
                                  float* __restrict__ XIN, int l) {
    int idx = blockIdx.x*blockDim.x + threadIdx.x;
    if (idx >= NBO) return;
    int o = idx % DOUT;
    int b = (idx / DOUT) % BB;
    int n = idx / (DOUT*BB);
    int src = ((l*BB + b)*NNODE + n)*DOUT + o;
    XIN[(n*BB + b)*CG + 64  + o] = h0[src];
    XIN[(n*BB + b)*CG + 128 + o] = c0[src];
}

__global__ void prep_step_kernel(const float* __restrict__ XA, float* __restrict__ XIN, int t) {
    int idx = blockIdx.x*blockDim.x + threadIdx.x;
    if (idx >= NBO) return;
    int o  = idx % DOUT;
    int nb = idx / DOUT;
    XIN[nb*CG + o] = XA[(long long)t*NBO + idx];
}

// -------- gate: per-node TC GEMM (64x128x960) + sigmoid + r*h ---------------
__global__ __launch_bounds__(256)
void gate_tc_kernel(const float* __restrict__ XG, const float* __restrict__ XIN,
                    const __nv_bfloat16* __restrict__ Wh, const __nv_bfloat16* __restrict__ Wl,
                    const float* __restrict__ bgn,
                    float* __restrict__ Z, float* __restrict__ RH)
{
    const int n = blockIdx.x;
    __shared__ __nv_bfloat16 sAh[64][40], sAl[64][40];
    __shared__ __nv_bfloat16 sBh[32][136], sBl[32][136];
    int tid = threadIdx.x, warp = tid >> 5, lane = tid & 31;
    int wm = (warp >> 1) * 16, wn = (warp & 1) * 64;

    float acc[8][4];
    #pragma unroll
    for (int i = 0; i < 8; i++)
        #pragma unroll
        for (int q = 0; q < 4; q++) acc[i][q] = 0.f;

    int ar = tid >> 2, ac8 = (tid & 3) * 8;     // A: 64 rows x 32 floats
    int br = tid >> 3, bc16 = (tid & 7) * 16;   // B: 32 rows x 128 halves
    const __nv_bfloat16* Wnh = Wh + (long long)n * GK * 128;
    const __nv_bfloat16* Wnl = Wl + (long long)n * GK * 128;

    float4 ra0, ra1;
    uint4 rbh0, rbh1, rbl0, rbl1;

#define GT_LOAD(kt_) { int kk0 = (kt_)*32; int ksup = kk0 / CG, cb = kk0 % CG;    \
    const float* Abase = (ksup == 0)                                               \
        ? XIN + (long long)(n*BB)*CG                                               \
        : XG  + (((long long)(ksup-1)*NNODE + n)*BB)*CG;                           \
    const float* ga = Abase + ar*CG + cb + ac8;                                    \
    ra0 = *(const float4*)ga; ra1 = *(const float4*)(ga + 4);                      \
    const __nv_bfloat16* gh = Wnh + (long long)(kk0 + br)*128 + bc16;              \
    const __nv_bfloat16* gl = Wnl + (long long)(kk0 + br)*128 + bc16;              \
    rbh0 = *(const uint4*)gh; rbh1 = *(const uint4*)(gh + 8);                      \
    rbl0 = *(const uint4*)gl; rbl1 = *(const uint4*)(gl + 8); }

#define GT_STORE() {                                                              \
    __nv_bfloat16* dh = &sAh[ar][ac8]; __nv_bfloat16* dl = &sAl[ar][ac8];          \
    split2(ra0.x, ra0.y, (__nv_bfloat162*)dh,     (__nv_bfloat162*)dl);            \
    split2(ra0.z, ra0.w, (__nv_bfloat162*)(dh+2), (__nv_bfloat162*)(dl+2));        \
    split2(ra1.x, ra1.y, (__nv_bfloat162*)(dh+4), (__nv_bfloat162*)(dl+4));        \
    split2(ra1.z, ra1.w, (__nv_bfloat162*)(dh+6), (__nv_bfloat162*)(dl+6));        \
    *(uint4*)&sBh[br][bc16]     = rbh0; *(uint4*)&sBh[br][bc16 + 8] = rbh1;        \
    *(uint4*)&sBl[br][bc16]     = rbl0; *(uint4*)&sBl[br][bc16 + 8] = rbl1; }

    const int NT = GK/32;   // 30
    GT_LOAD(0);
    for (int kt = 0; kt < NT; kt++) {
        __syncthreads();
        GT_STORE();
        __syncthreads();
        if (kt + 1 < NT) GT_LOAD(kt+1);

        #pragma unroll
        for (int ks = 0; ks < 2; ks++) {
            unsigned ah[4], al[4];
            {
                int row = wm + (lane & 15);
                int col = ks*16 + (lane >> 4) * 8;
                ldsm_x4(ah, (unsigned)__cvta_generic_to_shared(&sAh[row][col]));
                ldsm_x4(al, (unsigned)__cvta_generic_to_shared(&sAl[row][col]));
            }
            unsigned bh[8][2], bl[8][2];
            #pragma unroll
            for (int np = 0; np < 4; np++) {
                int k  = ks*16 + (lane & 15);
                int nn = wn + np*16 + (lane >> 4) * 8;
                unsigned r[4];
                ldsm_x4t(r, (unsigned)__cvta_generic_to_shared(&sBh[k][nn]));
                bh[np*2][0] = r[0]; bh[np*2][1] = r[1];
                bh[np*2+1][0] = r[2]; bh[np*2+1][1] = r[3];
                ldsm_x4t(r, (unsigned)__cvta_generic_to_shared(&sBl[k][nn]));
                bl[np*2][0] = r[0]; bl[np*2][1] = r[1];
                bl[np*2+1][0] = r[2]; bl[np*2+1][1] = r[3];
            }
            #pragma unroll
            for (int ni = 0; ni < 8; ni++) {
                mma16816(acc[ni], ah, bh[ni]);
                mma16816(acc[ni], ah, bl[ni]);
                mma16816(acc[ni], al, bh[ni]);
            }
        }
    }

    const float* brow = bgn + n*128;
    int g = lane >> 2, q = lane & 3;
    #pragma unroll
    for (int ni = 0; ni < 8; ni++) {
        #pragma unroll
        for (int d = 0; d < 4; d++) {
            int row = wm + g + ((d >= 2) ? 8 : 0);
            int col = wn + ni*8 + q*2 + (d & 1);
            float v = acc[ni][d] + brow[col];
            float s = 1.f / (1.f + expf(-v));
            if (col < 64) {
                Z[(n*BB + row)*DOUT + col] = s;
            } else {
                int oo = col - 64;
                float h = XIN[(long long)(n*BB + row)*CG + 64 + oo];
                RH[(n*BB + row)*DOUT + oo] = s * h;
            }
        }
    }
#undef GT_LOAD
#undef GT_STORE
}

// ------- candidate: per-node TC GEMM (64x64x640) + tanh + GRU/HiPPO ---------
__global__ __launch_bounds__(256)
void cand_tc_kernel(const float* __restrict__ XG, const float* __restrict__ XIN,
                    const float* __restrict__ RH, const float* __restrict__ XGR,
                    const __nv_bfloat16* __restrict__ Wh, const __nv_bfloat16* __restrict__ Wl,
                    const float* __restrict__ bcn, const float* __restrict__ Z,
                    float* __restrict__ XINout, float* __restrict__ OUT,
                    int t, int is_final, float ca, float cb)
{
    const int n = blockIdx.x;
    __shared__ __nv_bfloat16 sAh[64][40], sAl[64][40];
    __shared__ __nv_bfloat16 sBh[32][72], sBl[32][72];
    int tid = threadIdx.x, warp = tid >> 5, lane = tid & 31;
    int wm = (warp >> 1) * 16, wn = (warp & 1) * 32;

    float acc[4][4];
    #pragma unroll
    for (int i = 0; i < 4; i++)
        #pragma unroll
        for (int q = 0; q < 4; q++) acc[i][q] = 0.f;

    int ar = tid >> 2, ac8 = (tid & 3) * 8;     // A: 64x32 floats
    int br = tid >> 3, bc8 = (tid & 7) * 8;     // B: 32x64 halves
    const __nv_bfloat16* Wnh = Wh + (long long)n * CK * 64;
    const __nv_bfloat16* Wnl = Wl + (long long)n * CK * 64;

    float4 ra0, ra1;
    uint4 rbh0, rbl0;

#define CD_LOAD(kt_) { int kk0 = (kt_)*32; int ksup = kk0 / CC, cw = kk0 % CC;    \
    const float* Abase; int astride;                                               \
    if (cw < 64) { astride = CG;                                                   \
        Abase = (ksup == 0) ? XIN + (long long)(n*BB)*CG + cw                      \
                            : XG  + (((long long)(ksup-1)*NNODE + n)*BB)*CG + cw; } \
    else { astride = DOUT;                                                         \
        Abase = (ksup == 0) ? RH  + (long long)(n*BB)*DOUT + (cw - 64)             \
                            : XGR + (((long long)(ksup-1)*NNODE + n)*BB)*DOUT + (cw - 64); } \
    const float* ga = Abase + ar*astride + ac8;                                    \
    ra0 = *(const float4*)ga; ra1 = *(const float4*)(ga + 4);                      \
    rbh0 = *(const uint4*)(Wnh + (long long)(kk0 + br)*64 + bc8);                  \
    rbl0 = *(const uint4*)(Wnl + (long long)(kk0 + br)*64 + bc8); }

#define CD_STORE() {                                                              \
    __nv_bfloat16* dh = &sAh[ar][ac8]; __nv_bfloat16* dl = &sAl[ar][ac8];          \
    split2(ra0.x, ra0.y, (__nv_bfloat162*)dh,     (__nv_bfloat162*)dl);            \
    split2(ra0.z, ra0.w, (__nv_bfloat162*)(dh+2), (__nv_bfloat162*)(dl+2));        \
    split2(ra1.x, ra1.y, (__nv_bfloat162*)(dh+4), (__nv_bfloat162*)(dl+4));        \
    split2(ra1.z, ra1.w, (__nv_bfloat162*)(dh+6), (__nv_bfloat162*)(dl+6));        \
    *(uint4*)&sBh[br][bc8] = rbh0;                                                 \
    *(uint4*)&sBl[br][bc8] = rbl0; }

    const int NT = CK/32;   // 20
    CD_LOAD(0);
    for (int kt = 0; kt < NT; kt++) {
        __syncthreads();
        CD_STORE();
        __syncthreads();
        if (kt + 1 < NT) CD_LOAD(kt+1);

        #pragma unroll
        for (int ks = 0; ks < 2; ks++) {
            unsigned ah[4], al[4];
            {
                int row = wm + (lane & 15);
                int col = ks*16 + (lane >> 4) * 8;
                ldsm_x4(ah, (unsigned)__cvta_generic_to_shared(&sAh[row][col]));
                ldsm_x4(al, (unsigned)__cvta_generic_to_shared(&sAl[row][col]));
            }
            unsigned bh[4][2], bl[4][2];
            #pragma unroll
            for (int np = 0; np < 2; np++) {
                int k  = ks*16 + (lane & 15);
                int nn = wn + np*16 + (lane >> 4) * 8;
                unsigned r[4];
                ldsm_x4t(r, (unsigned)__cvta_generic_to_shared(&sBh[k][nn]));
                bh[np*2][0] = r[0]; bh[np*2][1] = r[1];
                bh[np*2+1][0] = r[2]; bh[np*2+1][1] = r[3];
                ldsm_x4t(r, (unsigned)__cvta_generic_to_shared(&sBl[k][nn]));
                bl[np*2][0] = r[0]; bl[np*2][1] = r[1];
                bl[np*2+1][0] = r[2]; bl[np*2+1][1] = r[3];
            }
            #pragma unroll
            for (int ni = 0; ni < 4; ni++) {
                mma16816(acc[ni], ah, bh[ni]);
                mma16816(acc[ni], ah, bl[ni]);
                mma16816(acc[ni], al, bh[ni]);
            }
        }
    }

    const float* brow = bcn + n*64;
    int g = lane >> 2, q = lane & 3;
    #pragma unroll
    for (int ni = 0; ni < 4; ni++) {
        #pragma unroll
        for (int d = 0; d < 4; d++) {
            int row = wm + g + ((d >= 2) ? 8 : 0);
            int col = wn + ni*8 + q*2 + (d & 1);
            float hc = tanhf(acc[ni][d] + brow[col]);
            float z  = Z[(n*BB + row)*DOUT + col];
            long long ih = (long long)(n*BB + row)*CG + 64 + col;
            float h_old = XINout[ih];
            float c_old = XINout[ih + 64];
            float h_new = z*h_old + (1.f - z)*hc;
            float c_new = ca*c_old + cb*h_new;
            XINout[ih]      = h_new;
            XINout[ih + 64] = c_new;
            if (is_final) OUT[(((long long)row*TT + t)*NNODE + n)*DOUT + col] = h_new;
            else          OUT[(((long long)t*NNODE + n)*BB + row)*DOUT + col] = h_new;
        }
    }
#undef CD_LOAD
#undef CD_STORE
}

// -------------------------------- driver ------------------------------------
extern "C" void kernel_launch(void* const* d_in, const int* in_sizes, int n_in,
                              void* d_out, int out_size)
{
    const float* x   = (const float*)d_in[0];
    const float* h0  = (const float*)d_in[1];
    const float* c0  = (const float*)d_in[2];
    const float* E   = (const float*)d_in[3];
    const float* adj = (const float*)d_in[4];
    const float* Wg  = (const float*)d_in[5];
    const float* bg  = (const float*)d_in[6];
    const float* Wc  = (const float*)d_in[7];
    const float* bc  = (const float*)d_in[8];
    float* out = (float*)d_out;
    (void)in_sizes; (void)n_in; (void)out_size;

    float *SS, *bgn, *bcn, *XA, *HS, *XIN, *RH, *XG, *XGR, *Z;
    __nv_bfloat16 *Shi, *Slo, *Wgh, *Wgl, *Wch, *Wcl;
    cudaGetSymbolAddress((void**)&SS,  g_SS);
    cudaGetSymbolAddress((void**)&Shi, g_Shi);
    cudaGetSymbolAddress((void**)&Slo, g_Slo);
    cudaGetSymbolAddress((void**)&Wgh, g_Wgh);
    cudaGetSymbolAddress((void**)&Wgl, g_Wgl);
    cudaGetSymbolAddress((void**)&bgn, g_bgn);
    cudaGetSymbolAddress((void**)&Wch, g_Wch);
    cudaGetSymbolAddress((void**)&Wcl, g_Wcl);
    cudaGetSymbolAddress((void**)&bcn, g_bcn);
    cudaGetSymbolAddress((void**)&XA,  g_XA);
    cudaGetSymbolAddress((void**)&HS,  g_HS);
    cudaGetSymbolAddress((void**)&XIN, g_XIN);
    cudaGetSymbolAddress((void**)&RH,  g_RH);
    cudaGetSymbolAddress((void**)&XG,  g_XG);
    cudaGetSymbolAddress((void**)&XGR, g_XGR);
    cudaGetSymbolAddress((void**)&Z,   g_Z);

    // ---- supports ----
    build_A_kernel   <<<NNODE, 256>>>(E,   SS + 0*NN);
    build_adjn_kernel<<<NNODE, 256>>>(adj, SS + 2*NN);
    dim3 g307((NNODE+127)/128, (NNODE+127)/128);
    sgemm_kernel<<<g307, 256>>>(NNODE, NNODE, NNODE, SS+0*NN, NNODE, SS+0*NN, NNODE, SS+1*NN, NNODE);
    cheb_fix_kernel<<<(NN+255)/256, 256>>>(SS + 1*NN);
    sgemm_kernel<<<g307, 256>>>(NNODE, NNODE, NNODE, SS+2*NN, NNODE, SS+2*NN, NNODE, SS+3*NN, NNODE);
    split_S_kernel<<<(MG*KTPAD + 255)/256, 256>>>(SS, Shi, Slo);

    for (int l = 0; l < 2; l++) {
        if (l == 0) window_avg_l0_kernel<<<(TNBO+255)/256, 256>>>(x, XA);
        else        window_avg_kernel   <<<(TNBO+255)/256, 256>>>(HS, XA);
        project_Wg_kernel<<<dim3(GK, NNODE), 128>>>(E, Wg, Wgh, Wgl, l);
        project_bg_kernel<<<NNODE, 128>>>(E, bg, bgn, l);
        project_Wc_kernel<<<dim3(CK, NNODE), 64>>>(E, Wc, Wch, Wcl, l);
        project_bc_kernel<<<NNODE, 64>>>(E, bc, bcn, l);
        init_state_kernel<<<(NBO+255)/256, 256>>>(h0, c0, XIN, l);

        for (int t = 0; t < TT; t++) {
            prep_step_kernel<<<(NBO+255)/256, 256>>>(XA, XIN, t);

            // XG = S @ XIN  (1228 x 12288 x 307)
            dim3 g1((BB*CG)/128, (MG+127)/128);
            tgemm_kernel<<<g1, 256>>>(MG, BB*CG, Shi, Slo, XIN, BB*CG, XG, BB*CG);

            gate_tc_kernel<<<NNODE, 256>>>(XG, XIN, Wgh, Wgl, bgn, Z, RH);

            // XGR = S @ RH  (1228 x 4096 x 307)
            dim3 g3((BB*DOUT)/128, (MG+127)/128);
            tgemm_kernel<<<g3, 256>>>(MG, BB*DOUT, Shi, Slo, RH, BB*DOUT, XGR, BB*DOUT);

            float ca = (float)t / (float)(t + 1);
            float cb = 1.f / (float)(t + 1);
            cand_tc_kernel<<<NNODE, 256>>>(XG, XIN, RH, XGR, Wch, Wcl, bcn, Z, XIN,
                                           (l == 1) ? out : HS, t, (l == 1), ca, cb);
        }
    }
}

// round 12
// speedup vs baseline: 2.5200x; 1.0649x over previous
#include <cuda_runtime.h>
#include <cuda_bf16.h>
#include <math.h>

// ---------------------------------------------------------------------------
// AVWDCRNN: adaptive-graph-conv GRU with HiPPO c-state.
// B=64, T=12, N=307, Din=Dout=64, L=2, De=16, K=5 supports.
// Round 12: arithmetic reverted to the PASSING R10 bf16 3-term emulation
// (fp16-single weights failed accuracy at 1.375e-3). Structural upgrades:
//  * all three mma kernels: k-tile 16, double-buffered smem, ONE sync/tile
//    (store(kt)->buf; sync; load(kt+1)->regs; mma(buf)). All static smem.
//  * prep_step fused into cand epilogue; init_state seeds x0 (-24 launches).
// ---------------------------------------------------------------------------

#define NNODE 307
#define BB    64
#define TT    12
#define DOUT  64
#define DE    16
#define KSUP  5
#define KR    4
#define CG    192
#define CC    128
#define GK    (KSUP*CG)      // 960
#define CK    (KSUP*CC)      // 640
#define NN    (NNODE*NNODE)
#define NB    (NNODE*BB)
#define NBO   (NB*DOUT)
#define TNBO  (TT*NBO)
#define MG    (KR*NNODE)     // 1228
#define KTPAD 320

// ------------------------------- scratch -----------------------------------
__device__ float g_SS [KR*NN];
__device__ __nv_bfloat16 g_Shi[MG*KTPAD];
__device__ __nv_bfloat16 g_Slo[MG*KTPAD];
__device__ __nv_bfloat16 g_Wgh[NNODE*GK*128];
__device__ __nv_bfloat16 g_Wgl[NNODE*GK*128];
__device__ float g_bgn[NNODE*128];
__device__ __nv_bfloat16 g_Wch[NNODE*CK*64];
__device__ __nv_bfloat16 g_Wcl[NNODE*CK*64];
__device__ float g_bcn[NNODE*64];
__device__ float g_XA [TNBO];
__device__ float g_HS [TNBO];
__device__ float g_XIN[NB*CG];
__device__ float g_RH [NB*DOUT];
__device__ float g_XG [KR*NB*CG];
__device__ float g_XGR[KR*NB*DOUT];
__device__ float g_Z  [NB*DOUT];

// --------------------------- asm helpers ------------------------------------
__device__ __forceinline__ void ldsm_x4(unsigned* r, unsigned addr) {
    asm volatile("ldmatrix.sync.aligned.m8n8.x4.shared.b16 {%0,%1,%2,%3}, [%4];"
                 : "=r"(r[0]), "=r"(r[1]), "=r"(r[2]), "=r"(r[3]) : "r"(addr));
}
__device__ __forceinline__ void ldsm_x4t(unsigned* r, unsigned addr) {
    asm volatile("ldmatrix.sync.aligned.m8n8.x4.trans.shared.b16 {%0,%1,%2,%3}, [%4];"
                 : "=r"(r[0]), "=r"(r[1]), "=r"(r[2]), "=r"(r[3]) : "r"(addr));
}
__device__ __forceinline__ void mma16816(float* d, const unsigned* a, const unsigned* b) {
    asm volatile("mma.sync.aligned.m16n8k16.row.col.f32.bf16.bf16.f32 "
                 "{%0,%1,%2,%3},{%4,%5,%6,%7},{%8,%9},{%0,%1,%2,%3};"
                 : "+f"(d[0]), "+f"(d[1]), "+f"(d[2]), "+f"(d[3])
                 : "r"(a[0]), "r"(a[1]), "r"(a[2]), "r"(a[3]), "r"(b[0]), "r"(b[1]));
}
__device__ __forceinline__ void split2(float x, float y, __nv_bfloat162* hi, __nv_bfloat162* lo) {
    __nv_bfloat16 h0 = __float2bfloat16(x), h1 = __float2bfloat16(y);
    *hi = __halves2bfloat162(h0, h1);
    *lo = __halves2bfloat162(__float2bfloat16(x - __bfloat162float(h0)),
                             __float2bfloat16(y - __bfloat162float(h1)));
}

// ------------------------- supports construction ----------------------------
__global__ void build_A_kernel(const float* __restrict__ E, float* __restrict__ A) {
    __shared__ float row[NNODE];
    __shared__ float er[DE];
    __shared__ float red[256];
    int i = blockIdx.x, tid = threadIdx.x;
    if (tid < DE) er[tid] = E[i*DE + tid];
    __syncthreads();
    for (int j = tid; j < NNODE; j += 256) {
        float s = 0.f;
        #pragma unroll
        for (int d = 0; d < DE; d++) s += er[d] * E[j*DE + d];
        row[j] = fmaxf(s, 0.f);
    }
    __syncthreads();
    float m = -1e30f;
    for (int j = tid; j < NNODE; j += 256) m = fmaxf(m, row[j]);
    red[tid] = m; __syncthreads();
    for (int s = 128; s > 0; s >>= 1) { if (tid < s) red[tid] = fmaxf(red[tid], red[tid+s]); __syncthreads(); }
    m = red[0]; __syncthreads();
    float sum = 0.f;
    for (int j = tid; j < NNODE; j += 256) { float e = expf(row[j]-m); row[j] = e; sum += e; }
    red[tid] = sum; __syncthreads();
    for (int s = 128; s > 0; s >>= 1) { if (tid < s) red[tid] += red[tid+s]; __syncthreads(); }
    float inv = 1.f / red[0];
    for (int j = tid; j < NNODE; j += 256) A[i*NNODE + j] = row[j] * inv;
}

__global__ void build_adjn_kernel(const float* __restrict__ adj, float* __restrict__ out) {
    __shared__ float red[256];
    int i = blockIdx.x, tid = threadIdx.x;
    float sum = 0.f;
    for (int j = tid; j < NNODE; j += 256) sum += adj[i*NNODE + j];
    red[tid] = sum; __syncthreads();
    for (int s = 128; s > 0; s >>= 1) { if (tid < s) red[tid] += red[tid+s]; __syncthreads(); }
    float inv = 1.f / (red[0] + 1e-8f);
    for (int j = tid; j < NNODE; j += 256) out[i*NNODE + j] = adj[i*NNODE + j] * inv;
}

__global__ void cheb_fix_kernel(float* __restrict__ S1) {
    int idx = blockIdx.x*blockDim.x + threadIdx.x;
    if (idx >= NN) return;
    float v = 2.f * S1[idx];
    if (idx / NNODE == idx % NNODE) v -= 1.f;
    S1[idx] = v;
}

__global__ void split_S_kernel(const float* __restrict__ SS,
                               __nv_bfloat16* __restrict__ Shi,
                               __nv_bfloat16* __restrict__ Slo) {
    int idx = blockIdx.x*blockDim.x + threadIdx.x;
    if (idx >= MG*KTPAD) return;
    int m = idx / KTPAD, k = idx % KTPAD;
    float v = (k < NNODE) ? SS[m*NNODE + k] : 0.f;
    __nv_bfloat16 h = __float2bfloat16(v);
    Shi[idx] = h;
    Slo[idx] = __float2bfloat16(v - __bfloat162float(h));
}

// ------------------------- generic SGEMM (row-major) ------------------------
__global__ __launch_bounds__(256)
void sgemm_kernel(int M, int N, int K,
                  const float* __restrict__ A, int lda,
                  const float* __restrict__ B, int ldb,
                  float* __restrict__ C, int ldc)
{
    __shared__ float As[8][128];
    __shared__ float Bs[8][128];
    int tid = threadIdx.x;
    int m0 = blockIdx.y * 128;
    int n0 = blockIdx.x * 128;
    int tx = tid % 16, ty = tid / 16;
    float acc[8][8];
    #pragma unroll
    for (int i = 0; i < 8; i++)
        #pragma unroll
        for (int j = 0; j < 8; j++) acc[i][j] = 0.f;

    int arow = tid / 2;
    int acol = (tid % 2) * 4;
    int brow = tid / 32;
    int bcol = (tid % 32) * 4;

    for (int kt = 0; kt < K; kt += 8) {
        #pragma unroll
        for (int j = 0; j < 4; j++) {
            int m = m0 + arow, k = kt + acol + j;
            As[acol + j][arow] = (m < M && k < K) ? A[(long long)m*lda + k] : 0.f;
        }
        #pragma unroll
        for (int j = 0; j < 4; j++) {
            int k = kt + brow, n = n0 + bcol + j;
            Bs[brow][bcol + j] = (k < K && n < N) ? B[(long long)k*ldb + n] : 0.f;
        }
        __syncthreads();
        #pragma unroll
        for (int kk = 0; kk < 8; kk++) {
            float a[8], b[8];
            #pragma unroll
            for (int i = 0; i < 4; i++) { a[i] = As[kk][ty*4+i]; a[4+i] = As[kk][64+ty*4+i]; }
            #pragma unroll
            for (int j = 0; j < 4; j++) { b[j] = Bs[kk][tx*4+j]; b[4+j] = Bs[kk][64+tx*4+j]; }
            #pragma unroll
            for (int i = 0; i < 8; i++)
                #pragma unroll
                for (int j = 0; j < 8; j++) acc[i][j] += a[i] * b[j];
        }
        __syncthreads();
    }
    #pragma unroll
    for (int i = 0; i < 8; i++) {
        int m = m0 + (i < 4 ? ty*4+i : 64 + ty*4 + (i-4));
        if (m >= M) continue;
        #pragma unroll
        for (int j = 0; j < 8; j++) {
            int n = n0 + (j < 4 ? tx*4+j : 64 + tx*4 + (j-4));
            if (n < N) C[(long long)m*ldc + n] = acc[i][j];
        }
    }
}

// --------------- tensor-core support GEMM: C = S @ B -------------------------
// k-tile 16, double-buffered, one sync per tile. bf16 3-term.
__global__ __launch_bounds__(256)
void tgemm_kernel(int M, int N,
                  const __nv_bfloat16* __restrict__ Ah,
                  const __nv_bfloat16* __restrict__ Al,
                  const float* __restrict__ B, int ldb,
                  float* __restrict__ C, int ldc)
{
    __shared__ __nv_bfloat16 sAh[2][128][24];
    __shared__ __nv_bfloat16 sAl[2][128][24];
    __shared__ __nv_bfloat16 sBh[2][16][136];
    __shared__ __nv_bfloat16 sBl[2][16][136];

    int tid  = threadIdx.x;
    int warp = tid >> 5, lane = tid & 31;
    int m0 = blockIdx.y * 128, n0 = blockIdx.x * 128;
    int wm = (warp >> 2) * 64, wn = (warp & 3) * 32;

    float acc[4][4][4];
    #pragma unroll
    for (int i = 0; i < 4; i++)
        #pragma unroll
        for (int j = 0; j < 4; j++)
            #pragma unroll
            for (int q = 0; q < 4; q++) acc[i][j][q] = 0.f;

    int ar = tid >> 1, ac = (tid & 1) * 8;      // A: 128 rows x 16 halves
    int bk = tid >> 4, bn = (tid & 15) * 8;     // B: 16 rows x 128 floats

    int srow = m0 + ar; if (srow > M-1) srow = M-1;
    const __nv_bfloat16* gAh = Ah + (long long)srow*KTPAD + ac;
    const __nv_bfloat16* gAl = Al + (long long)srow*KTPAD + ac;

    uint4 rah, ral;
    float4 rb0, rb1;

#define TG_LOAD(kt_) {                                                            \
    rah = *(const uint4*)(gAh + (kt_)*16);                                        \
    ral = *(const uint4*)(gAl + (kt_)*16);                                        \
    int kg = (kt_)*16 + bk;                                                       \
    if (kg < NNODE) { const float* gb = B + (long long)kg*ldb + n0 + bn;          \
        rb0 = *(const float4*)gb; rb1 = *(const float4*)(gb + 4); }               \
    else { rb0 = rb1 = make_float4(0.f,0.f,0.f,0.f); } }

#define TG_STORE(buf_) {                                                          \
    *(uint4*)&sAh[buf_][ar][ac] = rah;                                            \
    *(uint4*)&sAl[buf_][ar][ac] = ral;                                            \
    __nv_bfloat16* dh = &sBh[buf_][bk][bn]; __nv_bfloat16* dl = &sBl[buf_][bk][bn]; \
    split2(rb0.x, rb0.y, (__nv_bfloat162*)dh,     (__nv_bfloat162*)dl);           \
    split2(rb0.z, rb0.w, (__nv_bfloat162*)(dh+2), (__nv_bfloat162*)(dl+2));       \
    split2(rb1.x, rb1.y, (__nv_bfloat162*)(dh+4), (__nv_bfloat162*)(dl+4));       \
    split2(rb1.z, rb1.w, (__nv_bfloat162*)(dh+6), (__nv_bfloat162*)(dl+6)); }

    const int NT = KTPAD/16;   // 20
    TG_LOAD(0);
    int cur = 0;
    for (int kt = 0; kt < NT; kt++) {
        TG_STORE(cur);
        __syncthreads();
        if (kt + 1 < NT) TG_LOAD(kt+1);

        unsigned afh[4][4], afl[4][4], bfh[4][2], bfl[4][2];
        #pragma unroll
        for (int mi = 0; mi < 4; mi++) {
            int row = wm + mi*16 + (lane & 15);
            int col = (lane >> 4) * 8;
            ldsm_x4(afh[mi], (unsigned)__cvta_generic_to_shared(&sAh[cur][row][col]));
            ldsm_x4(afl[mi], (unsigned)__cvta_generic_to_shared(&sAl[cur][row][col]));
        }
        #pragma unroll
        for (int np = 0; np < 2; np++) {
            int k  = lane & 15;
            int nn = wn + np*16 + (lane >> 4) * 8;
            unsigned r[4];
            ldsm_x4t(r, (unsigned)__cvta_generic_to_shared(&sBh[cur][k][nn]));
            bfh[np*2][0] = r[0]; bfh[np*2][1] = r[1];
            bfh[np*2+1][0] = r[2]; bfh[np*2+1][1] = r[3];
            ldsm_x4t(r, (unsigned)__cvta_generic_to_shared(&sBl[cur][k][nn]));
            bfl[np*2][0] = r[0]; bfl[np*2][1] = r[1];
            bfl[np*2+1][0] = r[2]; bfl[np*2+1][1] = r[3];
        }
        #pragma unroll
        for (int mi = 0; mi < 4; mi++)
            #pragma unroll
            for (int ni = 0; ni < 4; ni++) {
                mma16816(acc[mi][ni], afh[mi], bfh[ni]);
                mma16816(acc[mi][ni], afh[mi], bfl[ni]);
                mma16816(acc[mi][ni], afl[mi], bfh[ni]);
            }
        cur ^= 1;
    }

    int g = lane >> 2, tq = lane & 3;
    #pragma unroll
    for (int mi = 0; mi < 4; mi++) {
        #pragma unroll
        for (int ni = 0; ni < 4; ni++) {
            int row = m0 + wm + mi*16 + g;
            int col = n0 + wn + ni*8 + tq*2;
            if (row < M)
                *(float2*)&C[(long long)row*ldc + col] = make_float2(acc[mi][ni][0], acc[mi][ni][1]);
            if (row + 8 < M)
                *(float2*)&C[(long long)(row+8)*ldc + col] = make_float2(acc[mi][ni][2], acc[mi][ni][3]);
        }
    }
#undef TG_LOAD
#undef TG_STORE
}

// ---------------------- per-node weight projection (bf16 hi/lo) -------------
__global__ void project_Wg_kernel(const float* __restrict__ E, const float* __restrict__ Wg,
                                  __nv_bfloat16* __restrict__ Wh, __nv_bfloat16* __restrict__ Wl, int l) {
    int kc = blockIdx.x, n = blockIdx.y, o = threadIdx.x;
    const float* er = E + n*DE;
    float acc = 0.f;
    #pragma unroll
    for (int d = 0; d < DE; d++) acc += er[d] * Wg[((l*DE + d)*GK + kc)*128 + o];
    __nv_bfloat16 h = __float2bfloat16(acc);
    long long idx = ((long long)n*GK + kc)*128 + o;
    Wh[idx] = h;
    Wl[idx] = __float2bfloat16(acc - __bfloat162float(h));
}
__global__ void project_Wc_kernel(const float* __restrict__ E, const float* __restrict__ Wc,
                                  __nv_bfloat16* __restrict__ Wh, __nv_bfloat16* __restrict__ Wl, int l) {
    int kc = blockIdx.x, n = blockIdx.y, o = threadIdx.x;
    const float* er = E + n*DE;
    float acc = 0.f;
    #pragma unroll
    for (int d = 0; d < DE; d++) acc += er[d] * Wc[((l*DE + d)*CK + kc)*64 + o];
    __nv_bfloat16 h = __float2bfloat16(acc);
    long long idx = ((long long)n*CK + kc)*64 + o;
    Wh[idx] = h;
    Wl[idx] = __float2bfloat16(acc - __bfloat162float(h));
}
__global__ void project_bg_kernel(const float* __restrict__ E, const float* __restrict__ bg,
                                  float* __restrict__ bgn, int l) {
    int n = blockIdx.x, o = threadIdx.x;
    float acc = 0.f;
    #pragma unroll
    for (int d = 0; d < DE; d++) acc += E[n*DE+d] * bg[(l*DE + d)*128 + o];
    bgn[n*128 + o] = acc;
}
__global__ void project_bc_kernel(const float* __restrict__ E, const float* __restrict__ bc,
                                  float* __restrict__ bcn, int l) {
    int n = blockIdx.x, o = threadIdx.x;
    float acc = 0.f;
    #pragma unroll
    for (int d = 0; d < DE; d++) acc += E[n*DE+d] * bc[(l*DE + d)*64 + o];
    bcn[n*64 + o] = acc;
}

// ----------------------------- data movement --------------------------------
__global__ void window_avg_l0_kernel(const float* __restrict__ x, float* __restrict__ XA) {
    long long idx = (long long)blockIdx.x*blockDim.x + threadIdx.x;
    if (idx >= TNBO) return;
    int c = (int)(idx % DOUT);
    int b = (int)((idx / DOUT) % BB);
    int n = (int)((idx / (DOUT*BB)) % NNODE);
    int t = (int)(idx / ((long long)DOUT*BB*NNODE));
    long long base = (((long long)b*TT + t)*NNODE + n)*DOUT + c;
    const long long dT = (long long)NNODE*DOUT;
    float v;
    if (t == 0 || t == TT-1) v = x[base];
    else v = (x[base - dT] + x[base] + x[base + dT]) * (1.f/3.f);
    XA[idx] = v;
}

__global__ void window_avg_kernel(const float* __restrict__ IN, float* __restrict__ XA) {
    int idx = blockIdx.x*blockDim.x + threadIdx.x;
    if (idx >= TNBO) return;
    int t = idx / NBO;
    if (t == 0 || t == TT-1) XA[idx] = IN[idx];
    else XA[idx] = (IN[idx-NBO] + IN[idx] + IN[idx+NBO]) * (1.f/3.f);
}

// seeds h,c AND x(t=0) into XIN
__global__ void init_state_kernel(const float* __restrict__ h0, const float* __restrict__ c0,
                                  const float* __restrict__ XA, float* __restrict__ XIN, int l) {
    int idx = blockIdx.x*blockDim.x + threadIdx.x;
    if (idx >= NBO) return;
    int o = idx % DOUT;
    int b = (idx / DOUT) % BB;
    int n = idx / (DOUT*BB);
    int src = ((l*BB + b)*NNODE + n)*DOUT + o;
    XIN[(n*BB + b)*CG + o]       = XA[idx];          // x at t=0 ([t=0][n][b][c] == idx)
    XIN[(n*BB + b)*CG + 64  + o] = h0[src];
    XIN[(n*BB + b)*CG + 128 + o] = c0[src];
}

// -------- gate: per-node TC GEMM (64x128x960) + sigmoid + r*h ---------------
// k-tile 16, double-buffered, one sync per tile, bf16 3-term.
__global__ __launch_bounds__(256)
void gate_tc_kernel(const float* __restrict__ XG, const float* __restrict__ XIN,
                    const __nv_bfloat16* __restrict__ Wh, const __nv_bfloat16* __restrict__ Wl,
                    const float* __restrict__ bgn,
                    float* __restrict__ Z, float* __restrict__ RH)
{
    const int n = blockIdx.x;
    __shared__ __nv_bfloat16 sAh[2][64][24], sAl[2][64][24];
    __shared__ __nv_bfloat16 sBh[2][16][136], sBl[2][16][136];
    int tid = threadIdx.x, warp = tid >> 5, lane = tid & 31;
    int wm = (warp >> 1) * 16, wn = (warp & 1) * 64;

    float acc[8][4];
    #pragma unroll
    for (int i = 0; i < 8; i++)
        #pragma unroll
        for (int q = 0; q < 4; q++) acc[i][q] = 0.f;

    int ar = tid >> 2, ac4 = (tid & 3) * 4;     // A: 64 rows x 16 floats
    int br = tid >> 4, bc8 = (tid & 15) * 8;    // B: 16 rows x 128 halves
    const __nv_bfloat16* Wnh = Wh + (long long)n * GK * 128;
    const __nv_bfloat16* Wnl = Wl + (long long)n * GK * 128;

    float4 ra;
    uint4 rbh, rbl;

#define GT_LOAD(kt_) { int kk0 = (kt_)*16; int ksup = kk0 / CG, cb = kk0 % CG;    \
    const float* Abase = (ksup == 0)                                               \
        ? XIN + (long long)(n*BB)*CG                                               \
        : XG  + (((long long)(ksup-1)*NNODE + n)*BB)*CG;                           \
    ra = *(const float4*)(Abase + ar*CG + cb + ac4);                               \
    const __nv_bfloat16* gh = Wnh + (long long)(kk0 + br)*128 + bc8;               \
    const __nv_bfloat16* gl = Wnl + (long long)(kk0 + br)*128 + bc8;               \
    rbh = *(const uint4*)gh; rbl = *(const uint4*)gl; }

#define GT_STORE(buf_) {                                                          \
    __nv_bfloat16* dh = &sAh[buf_][ar][ac4]; __nv_bfloat16* dl = &sAl[buf_][ar][ac4]; \
    split2(ra.x, ra.y, (__nv_bfloat162*)dh,     (__nv_bfloat162*)dl);              \
    split2(ra.z, ra.w, (__nv_bfloat162*)(dh+2), (__nv_bfloat162*)(dl+2));          \
    *(uint4*)&sBh[buf_][br][bc8] = rbh;                                            \
    *(uint4*)&sBl[buf_][br][bc8] = rbl; }

    const int NT = GK/16;   // 60
    GT_LOAD(0);
    int cur = 0;
    for (int kt = 0; kt < NT; kt++) {
        GT_STORE(cur);
        __syncthreads();
        if (kt + 1 < NT) GT_LOAD(kt+1);

        unsigned ah[4], al[4];
        {
            int row = wm + (lane & 15);
            int col = (lane >> 4) * 8;
            ldsm_x4(ah, (unsigned)__cvta_generic_to_shared(&sAh[cur][row][col]));
            ldsm_x4(al, (unsigned)__cvta_generic_to_shared(&sAl[cur][row][col]));
        }
        unsigned bh[8][2], bl[8][2];
        #pragma unroll
        for (int np = 0; np < 4; np++) {
            int k  = lane & 15;
            int nn = wn + np*16 + (lane >> 4) * 8;
            unsigned r[4];
            ldsm_x4t(r, (unsigned)__cvta_generic_to_shared(&sBh[cur][k][nn]));
            bh[np*2][0] = r[0]; bh[np*2][1] = r[1];
            bh[np*2+1][0] = r[2]; bh[np*2+1][1] = r[3];
            ldsm_x4t(r, (unsigned)__cvta_generic_to_shared(&sBl[cur][k][nn]));
            bl[np*2][0] = r[0]; bl[np*2][1] = r[1];
            bl[np*2+1][0] = r[2]; bl[np*2+1][1] = r[3];
        }
        #pragma unroll
        for (int ni = 0; ni < 8; ni++) {
            mma16816(acc[ni], ah, bh[ni]);
            mma16816(acc[ni], ah, bl[ni]);
            mma16816(acc[ni], al, bh[ni]);
        }
        cur ^= 1;
    }

    const float* brow = bgn + n*128;
    int g = lane >> 2, q = lane & 3;
    #pragma unroll
    for (int ni = 0; ni < 8; ni++) {
        #pragma unroll
        for (int d = 0; d < 4; d++) {
            int row = wm + g + ((d >= 2) ? 8 : 0);
            int col = wn + ni*8 + q*2 + (d & 1);
            float v = acc[ni][d] + brow[col];
            float s = 1.f / (1.f + expf(-v));
            if (col < 64) {
                Z[(n*BB + row)*DOUT + col] = s;
            } else {
                int oo = col - 64;
                float h = XIN[(long long)(n*BB + row)*CG + 64 + oo];
                RH[(n*BB + row)*DOUT + oo] = s * h;
            }
        }
    }
#undef GT_LOAD
#undef GT_STORE
}

// ------- candidate: per-node TC GEMM (64x64x640) + tanh + GRU/HiPPO ---------
// k-tile 16, double-buffered, one sync per tile. Epilogue stages next x.
__global__ __launch_bounds__(256)
void cand_tc_kernel(const float* __restrict__ XG, const float* __restrict__ XIN,
                    const float* __restrict__ RH, const float* __restrict__ XGR,
                    const __nv_bfloat16* __restrict__ Wh, const __nv_bfloat16* __restrict__ Wl,
                    const float* __restrict__ bcn, const float* __restrict__ Z,
                    const float* __restrict__ XA,
                    float* __restrict__ XINout, float* __restrict__ OUT,
                    int t, int is_final, float ca, float cb)
{
    const int n = blockIdx.x;
    __shared__ __nv_bfloat16 sAh[2][64][24], sAl[2][64][24];
    __shared__ __nv_bfloat16 sBh[2][16][72], sBl[2][16][72];
    int tid = threadIdx.x, warp = tid >> 5, lane = tid & 31;
    int wm = (warp >> 1) * 16, wn = (warp & 1) * 32;

    float acc[4][4];
    #pragma unroll
    for (int i = 0; i < 4; i++)
        #pragma unroll
        for (int q = 0; q < 4; q++) acc[i][q] = 0.f;

    int ar = tid >> 2, ac4 = (tid & 3) * 4;     // A: 64 rows x 16 floats
    int br = (tid & 127) >> 3, bc8 = (tid & 7) * 8;  // B: 16x64 halves (first 128 thr)
    bool bldr = (tid < 128);
    const __nv_bfloat16* Wnh = Wh + (long long)n * CK * 64;
    const __nv_bfloat16* Wnl = Wl + (long long)n * CK * 64;

    float4 ra;
    uint4 rbh, rbl;

#define CD_LOAD(kt_) { int kk0 = (kt_)*16; int ksup = kk0 / CC, cw = kk0 % CC;    \
    const float* Abase; int astride;                                               \
    if (cw < 64) { astride = CG;                                                   \
        Abase = (ksup == 0) ? XIN + (long long)(n*BB)*CG + cw                      \
                            : XG  + (((long long)(ksup-1)*NNODE + n)*BB)*CG + cw; } \
    else { astride = DOUT;                                                         \
        Abase = (ksup == 0) ? RH  + (long long)(n*BB)*DOUT + (cw - 64)             \
                            : XGR + (((long long)(ksup-1)*NNODE + n)*BB)*DOUT + (cw - 64); } \
    ra = *(const float4*)(Abase + ar*astride + ac4);                               \
    if (bldr) {                                                                    \
        rbh = *(const uint4*)(Wnh + (long long)(kk0 + br)*64 + bc8);               \
        rbl = *(const uint4*)(Wnl + (long long)(kk0 + br)*64 + bc8); } }

#define CD_STORE(buf_) {                                                          \
    __nv_bfloat16* dh = &sAh[buf_][ar][ac4]; __nv_bfloat16* dl = &sAl[buf_][ar][ac4]; \
    split2(ra.x, ra.y, (__nv_bfloat162*)dh,     (__nv_bfloat162*)dl);              \
    split2(ra.z, ra.w, (__nv_bfloat162*)(dh+2), (__nv_bfloat162*)(dl+2));          \
    if (bldr) {                                                                    \
        *(uint4*)&sBh[buf_][br][bc8] = rbh;                                        \
        *(uint4*)&sBl[buf_][br][bc8] = rbl; } }

    const int NT = CK/16;   // 40
    CD_LOAD(0);
    int cur = 0;
    for (int kt = 0; kt < NT; kt++) {
        CD_STORE(cur);
        __syncthreads();
        if (kt + 1 < NT) CD_LOAD(kt+1);

        unsigned ah[4], al[4];
        {
            int row = wm + (lane & 15);
            int col = (lane >> 4) * 8;
            ldsm_x4(ah, (unsigned)__cvta_generic_to_shared(&sAh[cur][row][col]));
            ldsm_x4(al, (unsigned)__cvta_generic_to_shared(&sAl[cur][row][col]));
        }
        unsigned bh[4][2], bl[4][2];
        #pragma unroll
        for (int np = 0; np < 2; np++) {
            int k  = lane & 15;
            int nn = wn + np*16 + (lane >> 4) * 8;
            unsigned r[4];
            ldsm_x4t(r, (unsigned)__cvta_generic_to_shared(&sBh[cur][k][nn]));
            bh[np*2][0] = r[0]; bh[np*2][1] = r[1];
            bh[np*2+1][0] = r[2]; bh[np*2+1][1] = r[3];
            ldsm_x4t(r, (unsigned)__cvta_generic_to_shared(&sBl[cur][k][nn]));
            bl[np*2][0] = r[0]; bl[np*2][1] = r[1];
            bl[np*2+1][0] = r[2]; bl[np*2+1][1] = r[3];
        }
        #pragma unroll
        for (int ni = 0; ni < 4; ni++) {
            mma16816(acc[ni], ah, bh[ni]);
            mma16816(acc[ni], ah, bl[ni]);
            mma16816(acc[ni], al, bh[ni]);
        }
        cur ^= 1;
    }

    const float* brow = bcn + n*64;
    int g = lane >> 2, q = lane & 3;
    #pragma unroll
    for (int ni = 0; ni < 4; ni++) {
        #pragma unroll
        for (int d = 0; d < 4; d++) {
            int row = wm + g + ((d >= 2) ? 8 : 0);
            int col = wn + ni*8 + q*2 + (d & 1);
            float hc = tanhf(acc[ni][d] + brow[col]);
            float z  = Z[(n*BB + row)*DOUT + col];
            long long ih = (long long)(n*BB + row)*CG + 64 + col;
            float h_old = XINout[ih];
            float c_old = XINout[ih + 64];
            float h_new = z*h_old + (1.f - z)*hc;
            float c_new = ca*c_old + cb*h_new;
            XINout[ih]      = h_new;
            XINout[ih + 64] = c_new;
            if (is_final) OUT[(((long long)row*TT + t)*NNODE + n)*DOUT + col] = h_new;
            else          OUT[(((long long)t*NNODE + n)*BB + row)*DOUT + col] = h_new;
            if (t + 1 < TT)   // stage next step's x (replaces prep_step)
                XINout[(long long)(n*BB + row)*CG + col] =
                    XA[(long long)(t+1)*NBO + (n*BB + row)*DOUT + col];
        }
    }
#undef CD_LOAD
#undef CD_STORE
}

// -------------------------------- driver ------------------------------------
extern "C" void kernel_launch(void* const* d_in, const int* in_sizes, int n_in,
                              void* d_out, int out_size)
{
    const float* x   = (const float*)d_in[0];
    const float* h0  = (const float*)d_in[1];
    const float* c0  = (const float*)d_in[2];
    const float* E   = (const float*)d_in[3];
    const float* adj = (const float*)d_in[4];
    const float* Wg  = (const float*)d_in[5];
    const float* bg  = (const float*)d_in[6];
    const float* Wc  = (const float*)d_in[7];
    const float* bc  = (const float*)d_in[8];
    float* out = (float*)d_out;
    (void)in_sizes; (void)n_in; (void)out_size;

    float *SS, *bgn, *bcn, *XA, *HS, *XIN, *RH, *XG, *XGR, *Z;
    __nv_bfloat16 *Shi, *Slo, *Wgh, *Wgl, *Wch, *Wcl;
    cudaGetSymbolAddress((void**)&SS,  g_SS);
    cudaGetSymbolAddress((void**)&Shi, g_Shi);
    cudaGetSymbolAddress((void**)&Slo, g_Slo);
    cudaGetSymbolAddress((void**)&Wgh, g_Wgh);
    cudaGetSymbolAddress((void**)&Wgl, g_Wgl);
    cudaGetSymbolAddress((void**)&bgn, g_bgn);
    cudaGetSymbolAddress((void**)&Wch, g_Wch);
    cudaGetSymbolAddress((void**)&Wcl, g_Wcl);
    cudaGetSymbolAddress((void**)&bcn, g_bcn);
    cudaGetSymbolAddress((void**)&XA,  g_XA);
    cudaGetSymbolAddress((void**)&HS,  g_HS);
    cudaGetSymbolAddress((void**)&XIN, g_XIN);
    cudaGetSymbolAddress((void**)&RH,  g_RH);
    cudaGetSymbolAddress((void**)&XG,  g_XG);
    cudaGetSymbolAddress((void**)&XGR, g_XGR);
    cudaGetSymbolAddress((void**)&Z,   g_Z);

    // ---- supports ----
    build_A_kernel   <<<NNODE, 256>>>(E,   SS + 0*NN);
    build_adjn_kernel<<<NNODE, 256>>>(adj, SS + 2*NN);
    dim3 g307((NNODE+127)/128, (NNODE+127)/128);
    sgemm_kernel<<<g307, 256>>>(NNODE, NNODE, NNODE, SS+0*NN, NNODE, SS+0*NN, NNODE, SS+1*NN, NNODE);
    cheb_fix_kernel<<<(NN+255)/256, 256>>>(SS + 1*NN);
    sgemm_kernel<<<g307, 256>>>(NNODE, NNODE, NNODE, SS+2*NN, NNODE, SS+2*NN, NNODE, SS+3*NN, NNODE);
    split_S_kernel<<<(MG*KTPAD + 255)/256, 256>>>(SS, Shi, Slo);

    for (int l = 0; l < 2; l++) {
        if (l == 0) window_avg_l0_kernel<<<(TNBO+255)/256, 256>>>(x, XA);
        else        window_avg_kernel   <<<(TNBO+255)/256, 256>>>(HS, XA);
        project_Wg_kernel<<<dim3(GK, NNODE), 128>>>(E, Wg, Wgh, Wgl, l);
        project_bg_kernel<<<NNODE, 128>>>(E, bg, bgn, l);
        project_Wc_kernel<<<dim3(CK, NNODE), 64>>>(E, Wc, Wch, Wcl, l);
        project_bc_kernel<<<NNODE, 64>>>(E, bc, bcn, l);
        init_state_kernel<<<(NBO+255)/256, 256>>>(h0, c0, XA, XIN, l);

        for (int t = 0; t < TT; t++) {
            // XG = S @ XIN  (1228 x 12288 x 307)
            dim3 g1((BB*CG)/128, (MG+127)/128);
            tgemm_kernel<<<g1, 256>>>(MG, BB*CG, Shi, Slo, XIN, BB*CG, XG, BB*CG);

            gate_tc_kernel<<<NNODE, 256>>>(XG, XIN, Wgh, Wgl, bgn, Z, RH);

            // XGR = S @ RH  (1228 x 4096 x 307)
            dim3 g3((BB*DOUT)/128, (MG+127)/128);
            tgemm_kernel<<<g3, 256>>>(MG, BB*DOUT, Shi, Slo, RH, BB*DOUT, XGR, BB*DOUT);

            float ca = (float)t / (float)(t + 1);
            float cb = 1.f / (float)(t + 1);
            cand_tc_kernel<<<NNODE, 256>>>(XG, XIN, RH, XGR, Wch, Wcl, bcn, Z, XA, XIN,
                                           (l == 1) ? out : HS, t, (l == 1), ca, cb);
        }
    }
}